// round 1
// baseline (speedup 1.0000x reference)
#include <cuda_runtime.h>
#include <cuda_bf16.h>
#include <math.h>

// ---------------- problem constants ----------------
#define NN 10000        // nodes per type
#define EE 60000        // edges per edge type
#define TT 2            // node types
#define NH 8            // heads
#define F0 2048         // input feat
#define F1 1024         // layer1 out feat (2*HID)
#define D1 128          // layer1 head dim
#define F2 512          // layer2 out feat (HID)
#define D2 64           // layer2 head dim
#define OUTF 8

// ---------------- scratch (static device, allocation-free) ----------------
// offsets in floats
#define SZ_TNF1 ((size_t)TT*NN*F1)      // 20,480,000
#define SZ_TNF2 ((size_t)TT*NN*F2)      // 10,240,000
#define SZ_ENF1 ((size_t)4*NN*F1)       // 40,960,000
#define SZ_ENF2 ((size_t)4*NN*F2)       // 20,480,000

#define OFF_K1   ((size_t)0)
#define OFF_Q1   (OFF_K1 + SZ_TNF1)
#define OFF_V1   (OFF_Q1 + SZ_TNF1)
#define OFF_KR1  (OFF_V1 + SZ_TNF1)
#define OFF_VR1  (OFF_KR1 + SZ_ENF1)
#define OFF_OUT1 (OFF_VR1 + SZ_ENF1)
#define OFF_ACT1 (OFF_OUT1 + SZ_TNF1)
#define OFF_H1   (OFF_ACT1 + SZ_TNF1)
#define OFF_K2   (OFF_H1 + SZ_TNF1)
#define OFF_Q2   (OFF_K2 + SZ_TNF2)
#define OFF_V2   (OFF_Q2 + SZ_TNF2)
#define OFF_KR2  (OFF_V2 + SZ_TNF2)
#define OFF_VR2  (OFF_KR2 + SZ_ENF2)
#define OFF_OUT2 (OFF_VR2 + SZ_ENF2)
#define OFF_ACT2 (OFF_OUT2 + SZ_TNF2)
#define OFF_H2   (OFF_ACT2 + SZ_TNF2)
#define OFF_ALPHA (OFF_H2 + SZ_TNF2)                 // 4*EE*NH = 1,920,000
#define OFF_M    (OFF_ALPHA + (size_t)4*EE*NH)       // 4*NN*NH = 320,000
#define OFF_S    (OFF_M + (size_t)4*NN*NH)
#define TOTAL_SCRATCH (OFF_S + (size_t)4*NN*NH)      // 309,760,000 floats (~1.24 GB)

__device__ float g_scratch[TOTAL_SCRATCH];

// ---------------- helpers ----------------
__device__ __forceinline__ unsigned ford(float f) {
    unsigned u = __float_as_uint(f);
    return (u >> 31) ? ~u : (u | 0x80000000u);
}
__device__ __forceinline__ float finv(unsigned u) {
    return (u >> 31) ? __uint_as_float(u & 0x7FFFFFFFu) : __uint_as_float(~u);
}

// ---------------- fill ----------------
__global__ void fill_f(float* p, float v, int n) {
    int i = blockIdx.x * blockDim.x + threadIdx.x;
    int stride = gridDim.x * blockDim.x;
    for (; i < n; i += stride) p[i] = v;
}

// ---------------- batched GEMM + optional bias ----------------
// C[z] = A[z] @ B[z] (+ bias[z]); row-major, arbitrary ld, batch via element strides.
template<int BM, int BN, int BK, int TM, int TN>
__global__ void gemm_bias_kernel(const float* __restrict__ A, const float* __restrict__ B,
                                 const float* __restrict__ bias, float* __restrict__ C,
                                 int M, int Nn, int K, int lda, int ldb, int ldc,
                                 size_t sA, size_t sB, size_t sBias, size_t sC)
{
    constexpr int THREADS = (BM / TM) * (BN / TN);
    __shared__ float As[BK][BM + 4];
    __shared__ float Bs[BK][BN];

    int z = blockIdx.z;
    A += (size_t)z * sA;
    B += (size_t)z * sB;
    C += (size_t)z * sC;
    if (bias) bias += (size_t)z * sBias;

    int bm = blockIdx.y * BM, bn = blockIdx.x * BN;
    int tid = threadIdx.x;
    int tx = tid % (BN / TN), ty = tid / (BN / TN);

    float acc[TM][TN];
#pragma unroll
    for (int i = 0; i < TM; i++)
#pragma unroll
        for (int j = 0; j < TN; j++) acc[i][j] = 0.f;

    for (int kt = 0; kt < K; kt += BK) {
#pragma unroll 4
        for (int i = tid; i < BM * BK; i += THREADS) {
            int m = i / BK, k = i % BK;
            int gm = bm + m;
            As[k][m] = (gm < M) ? A[(size_t)gm * lda + kt + k] : 0.f;
        }
#pragma unroll 4
        for (int i = tid; i < BK * BN; i += THREADS) {
            int k = i / BN, n = i % BN;
            int gn = bn + n;
            Bs[k][n] = (gn < Nn) ? B[(size_t)(kt + k) * ldb + gn] : 0.f;
        }
        __syncthreads();
#pragma unroll
        for (int k = 0; k < BK; k++) {
            float a[TM], b[TN];
#pragma unroll
            for (int i = 0; i < TM; i++) a[i] = As[k][ty * TM + i];
#pragma unroll
            for (int j = 0; j < TN; j++) b[j] = Bs[k][tx * TN + j];
#pragma unroll
            for (int i = 0; i < TM; i++)
#pragma unroll
                for (int j = 0; j < TN; j++) acc[i][j] = fmaf(a[i], b[j], acc[i][j]);
        }
        __syncthreads();
    }

#pragma unroll
    for (int i = 0; i < TM; i++) {
        int gm = bm + ty * TM + i;
        if (gm >= M) continue;
#pragma unroll
        for (int j = 0; j < TN; j++) {
            int gn = bn + tx * TN + j;
            if (gn >= Nn) continue;
            float v = acc[i][j];
            if (bias) v += bias[gn];
            C[(size_t)gm * ldc + gn] = v;
        }
    }
}

// ---------------- edge kernels ----------------
// warp per (edge, head): logits + atomic max
__global__ void edge_logits(const float* __restrict__ q, const float* __restrict__ kr,
                            const int* __restrict__ src, const int* __restrict__ dst,
                            const float* __restrict__ prel_row,
                            float* __restrict__ alpha, unsigned* __restrict__ mbuf,
                            float scale, int D, int F)
{
    int warp = (blockIdx.x * blockDim.x + threadIdx.x) >> 5;
    int lane = threadIdx.x & 31;
    if (warp >= EE * NH) return;
    int e = warp / NH, h = warp % NH;
    int sN = src[e], dN = dst[e];
    const float* qp = q + (size_t)dN * F + h * D;
    const float* kp = kr + (size_t)sN * F + h * D;
    float acc = 0.f;
    for (int i = lane; i < D; i += 32) acc = fmaf(qp[i], kp[i], acc);
#pragma unroll
    for (int o = 16; o; o >>= 1) acc += __shfl_down_sync(0xFFFFFFFFu, acc, o);
    if (lane == 0) {
        float v = acc * prel_row[h] * scale;
        alpha[(size_t)e * NH + h] = v;
        atomicMax(&mbuf[(size_t)dN * NH + h], ford(v));
    }
}

// thread per (edge, head): exp(alpha - m), atomic sum
__global__ void edge_expsum(const int* __restrict__ dst,
                            float* __restrict__ alpha,
                            const unsigned* __restrict__ mbuf, float* __restrict__ sbuf)
{
    int idx = blockIdx.x * blockDim.x + threadIdx.x;
    if (idx >= EE * NH) return;
    int e = idx / NH, h = idx % NH;
    int dN = dst[e];
    float m = finv(mbuf[(size_t)dN * NH + h]);
    float ex = expf(alpha[idx] - m);
    alpha[idx] = ex;
    atomicAdd(&sbuf[(size_t)dN * NH + h], ex);
}

// warp per (edge, head): normalized weight * v_rel scatter-add
__global__ void edge_aggregate(const float* __restrict__ vr,
                               const int* __restrict__ src, const int* __restrict__ dst,
                               const float* __restrict__ alpha, const float* __restrict__ sbuf,
                               float* __restrict__ out, int D, int F)
{
    int warp = (blockIdx.x * blockDim.x + threadIdx.x) >> 5;
    int lane = threadIdx.x & 31;
    if (warp >= EE * NH) return;
    int e = warp / NH, h = warp % NH;
    int sN = src[e], dN = dst[e];
    float w = alpha[(size_t)e * NH + h] / (sbuf[(size_t)dN * NH + h] + 1e-16f);
    const float* vp = vr + (size_t)sN * F + h * D;
    float* op = out + (size_t)dN * F + h * D;
    for (int i = lane; i < D; i += 32) atomicAdd(&op[i], vp[i] * w);
}

// ---------------- gelu (exact, erf) ----------------
__global__ void gelu_kernel(const float* __restrict__ in, float* __restrict__ out, int n)
{
    int i = blockIdx.x * blockDim.x + threadIdx.x;
    int stride = gridDim.x * blockDim.x;
    for (; i < n; i += stride) {
        float x = in[i];
        out[i] = 0.5f * x * (1.0f + erff(x * 0.70710678118654752440f));
    }
}

// ---------------- final linear + row softmax ----------------
__global__ void final_kernel(const float* __restrict__ h2, const float* __restrict__ W,
                             const float* __restrict__ b, float* __restrict__ out)
{
    int warp = (blockIdx.x * blockDim.x + threadIdx.x) >> 5;
    int lane = threadIdx.x & 31;
    if (warp >= TT * NN) return;
    const float* hp = h2 + (size_t)warp * F2;
    float acc[OUTF];
#pragma unroll
    for (int o = 0; o < OUTF; o++) acc[o] = 0.f;
    for (int f = lane; f < F2; f += 32) {
        float xv = hp[f];
        const float* wp = W + (size_t)f * OUTF;
#pragma unroll
        for (int o = 0; o < OUTF; o++) acc[o] = fmaf(xv, wp[o], acc[o]);
    }
#pragma unroll
    for (int o = 0; o < OUTF; o++) {
#pragma unroll
        for (int off = 16; off; off >>= 1) acc[o] += __shfl_down_sync(0xFFFFFFFFu, acc[o], off);
    }
    if (lane == 0) {
        float l[OUTF];
        float m = -1e30f;
#pragma unroll
        for (int o = 0; o < OUTF; o++) { l[o] = acc[o] + b[o]; m = fmaxf(m, l[o]); }
        float s = 0.f;
#pragma unroll
        for (int o = 0; o < OUTF; o++) { l[o] = expf(l[o] - m); s += l[o]; }
        float inv = 1.f / s;
        float* op = out + (size_t)warp * OUTF;
#pragma unroll
        for (int o = 0; o < OUTF; o++) op[o] = l[o] * inv;
    }
}

// ---------------- host-side launch helpers ----------------
static void gemm_big(const float* A, const float* B, const float* bias, float* C,
                     int M, int N, int K, int lda, int ldb, int ldc,
                     size_t sA, size_t sB, size_t sBias, size_t sC, int batch)
{
    dim3 grid((N + 127) / 128, (M + 127) / 128, batch);
    gemm_bias_kernel<128, 128, 16, 8, 8><<<grid, 256>>>(A, B, bias, C, M, N, K, lda, ldb, ldc,
                                                        sA, sB, sBias, sC);
}

static void gemm_small(const float* A, const float* B, const float* bias, float* C,
                       int M, int N, int K, int lda, int ldb, int ldc,
                       size_t sA, size_t sB, size_t sBias, size_t sC, int batch)
{
    dim3 grid((N + 63) / 64, (M + 63) / 64, batch);
    gemm_bias_kernel<64, 64, 16, 4, 4><<<grid, 256>>>(A, B, bias, C, M, N, K, lda, ldb, ldc,
                                                      sA, sB, sBias, sC);
}

extern "C" void kernel_launch(void* const* d_in, const int* in_sizes, int n_in,
                              void* d_out, int out_size)
{
    (void)in_sizes; (void)n_in; (void)out_size;
    const float* x     = (const float*)d_in[0];
    const int* ei[4]   = {(const int*)d_in[1], (const int*)d_in[2],
                          (const int*)d_in[3], (const int*)d_in[4]};
    const float* Wk1 = (const float*)d_in[5];  const float* bk1 = (const float*)d_in[6];
    const float* Wq1 = (const float*)d_in[7];  const float* bq1 = (const float*)d_in[8];
    const float* Wv1 = (const float*)d_in[9];  const float* bv1 = (const float*)d_in[10];
    const float* Wa1 = (const float*)d_in[11]; const float* ba1 = (const float*)d_in[12];
    const float* arel1 = (const float*)d_in[13];
    const float* mrel1 = (const float*)d_in[14];
    const float* prel1 = (const float*)d_in[15];
    const float* Wk2 = (const float*)d_in[16]; const float* bk2 = (const float*)d_in[17];
    const float* Wq2 = (const float*)d_in[18]; const float* bq2 = (const float*)d_in[19];
    const float* Wv2 = (const float*)d_in[20]; const float* bv2 = (const float*)d_in[21];
    const float* Wa2 = (const float*)d_in[22]; const float* ba2 = (const float*)d_in[23];
    const float* arel2 = (const float*)d_in[24];
    const float* mrel2 = (const float*)d_in[25];
    const float* prel2 = (const float*)d_in[26];
    const float* Wlin = (const float*)d_in[27]; const float* blin = (const float*)d_in[28];
    float* out = (float*)d_out;

    float* S = nullptr;
    cudaGetSymbolAddress((void**)&S, g_scratch);

    float* K1 = S + OFF_K1;  float* Q1 = S + OFF_Q1;  float* V1 = S + OFF_V1;
    float* KR1 = S + OFF_KR1; float* VR1 = S + OFF_VR1;
    float* OUT1 = S + OFF_OUT1; float* ACT1 = S + OFF_ACT1; float* H1 = S + OFF_H1;
    float* K2 = S + OFF_K2;  float* Q2 = S + OFF_Q2;  float* V2 = S + OFF_V2;
    float* KR2 = S + OFF_KR2; float* VR2 = S + OFF_VR2;
    float* OUT2 = S + OFF_OUT2; float* ACT2 = S + OFF_ACT2; float* H2 = S + OFF_H2;
    float* ALPHA = S + OFF_ALPHA;
    float* MB = S + OFF_M;   // used as unsigned (ordered-float); 0.0f bits == ordered minimum
    float* SB = S + OFF_S;

    const int st[4] = {0, 0, 1, 1};
    const int dt[4] = {0, 1, 0, 1};

    const int edgewarp_blocks = (EE * NH * 32 + 255) / 256;   // warp per (edge, head)
    const int edgethr_blocks  = (EE * NH + 255) / 256;

    // ============ LAYER 1 ============
    // projections (batched over T)
    gemm_big(x, Wk1, bk1, K1, NN, F1, F0, F0, F1, F1,
             (size_t)NN * F0, (size_t)F0 * F1, F1, (size_t)NN * F1, TT);
    gemm_big(x, Wq1, bq1, Q1, NN, F1, F0, F0, F1, F1,
             (size_t)NN * F0, (size_t)F0 * F1, F1, (size_t)NN * F1, TT);
    gemm_big(x, Wv1, bv1, V1, NN, F1, F0, F0, F1, F1,
             (size_t)NN * F0, (size_t)F0 * F1, F1, (size_t)NN * F1, TT);

    // rel transforms (batched over heads)
    for (int e = 0; e < 4; e++) {
        gemm_small(K1 + (size_t)st[e] * NN * F1, arel1 + (size_t)e * NH * D1 * D1, nullptr,
                   KR1 + (size_t)e * NN * F1, NN, D1, D1, F1, D1, F1,
                   (size_t)D1, (size_t)D1 * D1, 0, (size_t)D1, NH);
        gemm_small(V1 + (size_t)st[e] * NN * F1, mrel1 + (size_t)e * NH * D1 * D1, nullptr,
                   VR1 + (size_t)e * NN * F1, NN, D1, D1, F1, D1, F1,
                   (size_t)D1, (size_t)D1 * D1, 0, (size_t)D1, NH);
    }

    // edge phase
    fill_f<<<512, 256>>>(MB, 0.f, 4 * NN * NH);
    fill_f<<<512, 256>>>(SB, 0.f, 4 * NN * NH);
    fill_f<<<2048, 256>>>(OUT1, 0.f, (int)SZ_TNF1);
    {
        float scale = 1.f / sqrtf((float)D1);
        for (int e = 0; e < 4; e++)
            edge_logits<<<edgewarp_blocks, 256>>>(Q1 + (size_t)dt[e] * NN * F1,
                KR1 + (size_t)e * NN * F1, ei[e], ei[e] + EE, prel1 + e * NH,
                ALPHA + (size_t)e * EE * NH, (unsigned*)(MB + (size_t)e * NN * NH), scale, D1, F1);
        for (int e = 0; e < 4; e++)
            edge_expsum<<<edgethr_blocks, 256>>>(ei[e] + EE, ALPHA + (size_t)e * EE * NH,
                (const unsigned*)(MB + (size_t)e * NN * NH), SB + (size_t)e * NN * NH);
        for (int e = 0; e < 4; e++)
            edge_aggregate<<<edgewarp_blocks, 256>>>(VR1 + (size_t)e * NN * F1,
                ei[e], ei[e] + EE, ALPHA + (size_t)e * EE * NH, SB + (size_t)e * NN * NH,
                OUT1 + (size_t)dt[e] * NN * F1, D1, F1);
    }

    gelu_kernel<<<2048, 256>>>(OUT1, ACT1, (int)SZ_TNF1);
    gemm_big(ACT1, Wa1, ba1, H1, NN, F1, F1, F1, F1, F1,
             (size_t)NN * F1, (size_t)F1 * F1, F1, (size_t)NN * F1, TT);

    // ============ LAYER 2 ============
    gemm_big(H1, Wk2, bk2, K2, NN, F2, F1, F1, F2, F2,
             (size_t)NN * F1, (size_t)F1 * F2, F2, (size_t)NN * F2, TT);
    gemm_big(H1, Wq2, bq2, Q2, NN, F2, F1, F1, F2, F2,
             (size_t)NN * F1, (size_t)F1 * F2, F2, (size_t)NN * F2, TT);
    gemm_big(H1, Wv2, bv2, V2, NN, F2, F1, F1, F2, F2,
             (size_t)NN * F1, (size_t)F1 * F2, F2, (size_t)NN * F2, TT);

    for (int e = 0; e < 4; e++) {
        gemm_small(K2 + (size_t)st[e] * NN * F2, arel2 + (size_t)e * NH * D2 * D2, nullptr,
                   KR2 + (size_t)e * NN * F2, NN, D2, D2, F2, D2, F2,
                   (size_t)D2, (size_t)D2 * D2, 0, (size_t)D2, NH);
        gemm_small(V2 + (size_t)st[e] * NN * F2, mrel2 + (size_t)e * NH * D2 * D2, nullptr,
                   VR2 + (size_t)e * NN * F2, NN, D2, D2, F2, D2, F2,
                   (size_t)D2, (size_t)D2 * D2, 0, (size_t)D2, NH);
    }

    fill_f<<<512, 256>>>(MB, 0.f, 4 * NN * NH);
    fill_f<<<512, 256>>>(SB, 0.f, 4 * NN * NH);
    fill_f<<<2048, 256>>>(OUT2, 0.f, (int)SZ_TNF2);
    {
        float scale = 1.f / sqrtf((float)D2);
        for (int e = 0; e < 4; e++)
            edge_logits<<<edgewarp_blocks, 256>>>(Q2 + (size_t)dt[e] * NN * F2,
                KR2 + (size_t)e * NN * F2, ei[e], ei[e] + EE, prel2 + e * NH,
                ALPHA + (size_t)e * EE * NH, (unsigned*)(MB + (size_t)e * NN * NH), scale, D2, F2);
        for (int e = 0; e < 4; e++)
            edge_expsum<<<edgethr_blocks, 256>>>(ei[e] + EE, ALPHA + (size_t)e * EE * NH,
                (const unsigned*)(MB + (size_t)e * NN * NH), SB + (size_t)e * NN * NH);
        for (int e = 0; e < 4; e++)
            edge_aggregate<<<edgewarp_blocks, 256>>>(VR2 + (size_t)e * NN * F2,
                ei[e], ei[e] + EE, ALPHA + (size_t)e * EE * NH, SB + (size_t)e * NN * NH,
                OUT2 + (size_t)dt[e] * NN * F2, D2, F2);
    }

    gelu_kernel<<<2048, 256>>>(OUT2, ACT2, (int)SZ_TNF2);
    gemm_big(ACT2, Wa2, ba2, H2, NN, F2, F2, F2, F2, F2,
             (size_t)NN * F2, (size_t)F2 * F2, F2, (size_t)NN * F2, TT);

    // ============ final linear + softmax ============
    final_kernel<<<(TT * NN * 32 + 255) / 256, 256>>>(H2, Wlin, blin, out);
}

// round 2
// speedup vs baseline: 2.8121x; 2.8121x over previous
#include <cuda_runtime.h>
#include <cuda_bf16.h>
#include <math.h>
#include <stdint.h>

// ---------------- problem constants ----------------
#define NN 10000        // nodes per type
#define EE 60000        // edges per edge type
#define TT 2            // node types
#define NH 8            // heads
#define F0 2048         // input feat
#define F1 1024         // layer1 out feat (2*HID)
#define D1 128          // layer1 head dim
#define F2 512          // layer2 out feat (HID)
#define D2 64           // layer2 head dim
#define OUTF 8

// ---------------- scratch (static device, allocation-free) ----------------
#define SZ_TNF1 ((size_t)TT*NN*F1)
#define SZ_TNF2 ((size_t)TT*NN*F2)
#define SZ_ENF1 ((size_t)4*NN*F1)
#define SZ_ENF2 ((size_t)4*NN*F2)

#define OFF_K1   ((size_t)0)
#define OFF_Q1   (OFF_K1 + SZ_TNF1)
#define OFF_V1   (OFF_Q1 + SZ_TNF1)
#define OFF_KR1  (OFF_V1 + SZ_TNF1)
#define OFF_VR1  (OFF_KR1 + SZ_ENF1)
#define OFF_OUT1 (OFF_VR1 + SZ_ENF1)
#define OFF_ACT1 (OFF_OUT1 + SZ_TNF1)
#define OFF_H1   (OFF_ACT1 + SZ_TNF1)
#define OFF_K2   (OFF_H1 + SZ_TNF1)
#define OFF_Q2   (OFF_K2 + SZ_TNF2)
#define OFF_V2   (OFF_Q2 + SZ_TNF2)
#define OFF_KR2  (OFF_V2 + SZ_TNF2)
#define OFF_VR2  (OFF_KR2 + SZ_ENF2)
#define OFF_OUT2 (OFF_VR2 + SZ_ENF2)
#define OFF_ACT2 (OFF_OUT2 + SZ_TNF2)
#define OFF_H2   (OFF_ACT2 + SZ_TNF2)
#define OFF_ALPHA (OFF_H2 + SZ_TNF2)
#define OFF_M    (OFF_ALPHA + (size_t)4*EE*NH)
#define OFF_S    (OFF_M + (size_t)4*NN*NH)
#define TOTAL_SCRATCH (OFF_S + (size_t)4*NN*NH)

__device__ float g_scratch[TOTAL_SCRATCH];

// ---------------- helpers ----------------
__device__ __forceinline__ unsigned ford(float f) {
    unsigned u = __float_as_uint(f);
    return (u >> 31) ? ~u : (u | 0x80000000u);
}
__device__ __forceinline__ float finv(unsigned u) {
    return (u >> 31) ? __uint_as_float(u & 0x7FFFFFFFu) : __uint_as_float(~u);
}
__device__ __forceinline__ uint32_t f2tf(float f) {
    uint32_t r;
    asm("cvt.rna.tf32.f32 %0, %1;" : "=r"(r) : "f"(f));
    return r;
}
__device__ __forceinline__ void mma_tf32(float& c0, float& c1, float& c2, float& c3,
                                         uint32_t a0, uint32_t a1, uint32_t a2, uint32_t a3,
                                         uint32_t b0, uint32_t b1) {
    asm volatile("mma.sync.aligned.m16n8k8.row.col.f32.tf32.tf32.f32 "
                 "{%0,%1,%2,%3}, {%4,%5,%6,%7}, {%8,%9}, {%0,%1,%2,%3};"
                 : "+f"(c0), "+f"(c1), "+f"(c2), "+f"(c3)
                 : "r"(a0), "r"(a1), "r"(a2), "r"(a3), "r"(b0), "r"(b1));
}

// ---------------- fill ----------------
__global__ void fill_f(float* p, float v, int n) {
    int i = blockIdx.x * blockDim.x + threadIdx.x;
    int stride = gridDim.x * blockDim.x;
    for (; i < n; i += stride) p[i] = v;
}

// ---------------- TF32 tensor-core GEMM ----------------
// C[z] = A[z] @ B[z] (+ bias[z]); A row-major [M,lda], B row-major [K,ldb], C [M,ldc].
// Tile 128x128x32, 256 threads (8 warps: 2 along M x 4 along N, warp tile 64x32).
#define BM 128
#define BN 128
#define BKK 32
#define PADA 4
#define PADB 8

__global__ __launch_bounds__(256, 2)
void gemm_tf32_kernel(const float* __restrict__ A, const float* __restrict__ B,
                      const float* __restrict__ bias, float* __restrict__ C,
                      int M, int Nn, int K, int lda, int ldb, int ldc,
                      size_t sA, size_t sB, size_t sBias, size_t sC)
{
    __shared__ uint32_t As[BM][BKK + PADA];   // [m][k]
    __shared__ uint32_t Bs[BKK][BN + PADB];   // [k][n]

    int z = blockIdx.z;
    A += (size_t)z * sA;
    B += (size_t)z * sB;
    C += (size_t)z * sC;
    if (bias) bias += (size_t)z * sBias;

    int bm = blockIdx.y * BM, bn = blockIdx.x * BN;
    int tid = threadIdx.x;
    int lane = tid & 31;
    int w = tid >> 5;
    int wm = (w & 1) * 64;        // warp M offset within block
    int wn = (w >> 1) * 32;       // warp N offset within block
    int tg = lane & 3;            // thread-in-group
    int rowg = lane >> 2;         // group id

    float acc[4][4][4];
#pragma unroll
    for (int i = 0; i < 4; i++)
#pragma unroll
        for (int j = 0; j < 4; j++)
#pragma unroll
            for (int r = 0; r < 4; r++) acc[i][j][r] = 0.f;

    // A tile load mapping: 128 rows x 8 float4/row = 1024 float4, 4 per thread
    int a_row0 = tid >> 3;            // 0..31, +32 per pass
    int a_c4 = (tid & 7) * 4;         // k offset within BKK
    // B tile load mapping: 32 rows x 32 float4/row = 1024 float4, 4 per thread
    int b_row0 = tid >> 5;            // 0..7, +8 per pass
    int b_c4 = (tid & 31) * 4;        // n offset within BN

    for (int kt = 0; kt < K; kt += BKK) {
        // ---- load A tile ----
#pragma unroll
        for (int p = 0; p < 4; p++) {
            int m = a_row0 + p * 32;
            int gm = bm + m;
            float4 v;
            if (gm < M) v = *(const float4*)(A + (size_t)gm * lda + kt + a_c4);
            else v = make_float4(0.f, 0.f, 0.f, 0.f);
            As[m][a_c4 + 0] = f2tf(v.x);
            As[m][a_c4 + 1] = f2tf(v.y);
            As[m][a_c4 + 2] = f2tf(v.z);
            As[m][a_c4 + 3] = f2tf(v.w);
        }
        // ---- load B tile ----
#pragma unroll
        for (int p = 0; p < 4; p++) {
            int k = b_row0 + p * 8;
            int gn = bn + b_c4;
            float4 v;
            if (gn + 3 < Nn) {
                v = *(const float4*)(B + (size_t)(kt + k) * ldb + gn);
            } else {
                v.x = (gn + 0 < Nn) ? B[(size_t)(kt + k) * ldb + gn + 0] : 0.f;
                v.y = (gn + 1 < Nn) ? B[(size_t)(kt + k) * ldb + gn + 1] : 0.f;
                v.z = (gn + 2 < Nn) ? B[(size_t)(kt + k) * ldb + gn + 2] : 0.f;
                v.w = (gn + 3 < Nn) ? B[(size_t)(kt + k) * ldb + gn + 3] : 0.f;
            }
            Bs[k][b_c4 + 0] = f2tf(v.x);
            Bs[k][b_c4 + 1] = f2tf(v.y);
            Bs[k][b_c4 + 2] = f2tf(v.z);
            Bs[k][b_c4 + 3] = f2tf(v.w);
        }
        __syncthreads();

        // ---- compute ----
#pragma unroll
        for (int ks = 0; ks < BKK / 8; ks++) {
            int k0 = ks * 8;
            uint32_t af[4][4], bf[4][2];
#pragma unroll
            for (int mt = 0; mt < 4; mt++) {
                int mrow = wm + mt * 16 + rowg;
                af[mt][0] = As[mrow][k0 + tg];
                af[mt][1] = As[mrow + 8][k0 + tg];
                af[mt][2] = As[mrow][k0 + tg + 4];
                af[mt][3] = As[mrow + 8][k0 + tg + 4];
            }
#pragma unroll
            for (int nt = 0; nt < 4; nt++) {
                int ncol = wn + nt * 8 + rowg;
                bf[nt][0] = Bs[k0 + tg][ncol];
                bf[nt][1] = Bs[k0 + tg + 4][ncol];
            }
#pragma unroll
            for (int mt = 0; mt < 4; mt++)
#pragma unroll
                for (int nt = 0; nt < 4; nt++)
                    mma_tf32(acc[mt][nt][0], acc[mt][nt][1], acc[mt][nt][2], acc[mt][nt][3],
                             af[mt][0], af[mt][1], af[mt][2], af[mt][3],
                             bf[nt][0], bf[nt][1]);
        }
        __syncthreads();
    }

    // ---- epilogue ----
#pragma unroll
    for (int mt = 0; mt < 4; mt++) {
#pragma unroll
        for (int nt = 0; nt < 4; nt++) {
            int gm0 = bm + wm + mt * 16 + rowg;
            int gn0 = bn + wn + nt * 8 + tg * 2;
            float b0 = 0.f, b1 = 0.f;
            if (bias) {
                if (gn0 < Nn) b0 = bias[gn0];
                if (gn0 + 1 < Nn) b1 = bias[gn0 + 1];
            }
            if (gm0 < M) {
                if (gn0 < Nn)     C[(size_t)gm0 * ldc + gn0]     = acc[mt][nt][0] + b0;
                if (gn0 + 1 < Nn) C[(size_t)gm0 * ldc + gn0 + 1] = acc[mt][nt][1] + b1;
            }
            if (gm0 + 8 < M) {
                if (gn0 < Nn)     C[(size_t)(gm0 + 8) * ldc + gn0]     = acc[mt][nt][2] + b0;
                if (gn0 + 1 < Nn) C[(size_t)(gm0 + 8) * ldc + gn0 + 1] = acc[mt][nt][3] + b1;
            }
        }
    }
}

// ---------------- edge kernels ----------------
// warp per (edge, head): logits + atomic max (vectorized loads)
template<int D>
__global__ void edge_logits(const float* __restrict__ q, const float* __restrict__ kr,
                            const int* __restrict__ src, const int* __restrict__ dst,
                            const float* __restrict__ prel_row,
                            float* __restrict__ alpha, unsigned* __restrict__ mbuf,
                            float scale, int F)
{
    int warp = (blockIdx.x * blockDim.x + threadIdx.x) >> 5;
    int lane = threadIdx.x & 31;
    if (warp >= EE * NH) return;
    int e = warp / NH, h = warp % NH;
    int sN = src[e], dN = dst[e];
    const float* qp = q + (size_t)dN * F + h * D;
    const float* kp = kr + (size_t)sN * F + h * D;
    float acc = 0.f;
#pragma unroll
    for (int i = lane * 4; i < D; i += 128) {
        float4 a = *(const float4*)(qp + i);
        float4 b = *(const float4*)(kp + i);
        acc = fmaf(a.x, b.x, acc);
        acc = fmaf(a.y, b.y, acc);
        acc = fmaf(a.z, b.z, acc);
        acc = fmaf(a.w, b.w, acc);
    }
#pragma unroll
    for (int o = 16; o; o >>= 1) acc += __shfl_down_sync(0xFFFFFFFFu, acc, o);
    if (lane == 0) {
        float v = acc * prel_row[h] * scale;
        alpha[(size_t)e * NH + h] = v;
        atomicMax(&mbuf[(size_t)dN * NH + h], ford(v));
    }
}

// thread per (edge, head): exp(alpha - m), atomic sum
__global__ void edge_expsum(const int* __restrict__ dst,
                            float* __restrict__ alpha,
                            const unsigned* __restrict__ mbuf, float* __restrict__ sbuf)
{
    int idx = blockIdx.x * blockDim.x + threadIdx.x;
    if (idx >= EE * NH) return;
    int e = idx / NH, h = idx % NH;
    int dN = dst[e];
    float m = finv(mbuf[(size_t)dN * NH + h]);
    float ex = expf(alpha[idx] - m);
    alpha[idx] = ex;
    atomicAdd(&sbuf[(size_t)dN * NH + h], ex);
}

// warp per (edge, head): normalized weight * v_rel scatter-add (float4 atomics)
template<int D>
__global__ void edge_aggregate(const float* __restrict__ vr,
                               const int* __restrict__ src, const int* __restrict__ dst,
                               const float* __restrict__ alpha, const float* __restrict__ sbuf,
                               float* __restrict__ out, int F)
{
    int warp = (blockIdx.x * blockDim.x + threadIdx.x) >> 5;
    int lane = threadIdx.x & 31;
    if (warp >= EE * NH) return;
    int e = warp / NH, h = warp % NH;
    int sN = src[e], dN = dst[e];
    float w = alpha[(size_t)e * NH + h] / (sbuf[(size_t)dN * NH + h] + 1e-16f);
    const float* vp = vr + (size_t)sN * F + h * D;
    float* op = out + (size_t)dN * F + h * D;
#pragma unroll
    for (int i = lane * 4; i < D; i += 128) {
        float4 v = *(const float4*)(vp + i);
        float4 c = make_float4(v.x * w, v.y * w, v.z * w, v.w * w);
        atomicAdd((float4*)(op + i), c);
    }
}

// ---------------- gelu (exact, erf) ----------------
__global__ void gelu_kernel(const float* __restrict__ in, float* __restrict__ out, int n)
{
    int i = (blockIdx.x * blockDim.x + threadIdx.x) * 4;
    int stride = gridDim.x * blockDim.x * 4;
    for (; i < n; i += stride) {
        float4 x = *(const float4*)(in + i);
        float4 r;
        r.x = 0.5f * x.x * (1.0f + erff(x.x * 0.70710678118654752440f));
        r.y = 0.5f * x.y * (1.0f + erff(x.y * 0.70710678118654752440f));
        r.z = 0.5f * x.z * (1.0f + erff(x.z * 0.70710678118654752440f));
        r.w = 0.5f * x.w * (1.0f + erff(x.w * 0.70710678118654752440f));
        *(float4*)(out + i) = r;
    }
}

// ---------------- final linear + row softmax ----------------
__global__ void final_kernel(const float* __restrict__ h2, const float* __restrict__ W,
                             const float* __restrict__ b, float* __restrict__ out)
{
    int warp = (blockIdx.x * blockDim.x + threadIdx.x) >> 5;
    int lane = threadIdx.x & 31;
    if (warp >= TT * NN) return;
    const float* hp = h2 + (size_t)warp * F2;
    float acc[OUTF];
#pragma unroll
    for (int o = 0; o < OUTF; o++) acc[o] = 0.f;
    for (int f = lane; f < F2; f += 32) {
        float xv = hp[f];
        const float* wp = W + (size_t)f * OUTF;
#pragma unroll
        for (int o = 0; o < OUTF; o++) acc[o] = fmaf(xv, wp[o], acc[o]);
    }
#pragma unroll
    for (int o = 0; o < OUTF; o++) {
#pragma unroll
        for (int off = 16; off; off >>= 1) acc[o] += __shfl_down_sync(0xFFFFFFFFu, acc[o], off);
    }
    if (lane == 0) {
        float l[OUTF];
        float m = -1e30f;
#pragma unroll
        for (int o = 0; o < OUTF; o++) { l[o] = acc[o] + b[o]; m = fmaxf(m, l[o]); }
        float s = 0.f;
#pragma unroll
        for (int o = 0; o < OUTF; o++) { l[o] = expf(l[o] - m); s += l[o]; }
        float inv = 1.f / s;
        float* op = out + (size_t)warp * OUTF;
#pragma unroll
        for (int o = 0; o < OUTF; o++) op[o] = l[o] * inv;
    }
}

// ---------------- host-side launch helper ----------------
static void gemm_tf32(const float* A, const float* B, const float* bias, float* C,
                      int M, int N, int K, int lda, int ldb, int ldc,
                      size_t sA, size_t sB, size_t sBias, size_t sC, int batch)
{
    dim3 grid((N + BN - 1) / BN, (M + BM - 1) / BM, batch);
    gemm_tf32_kernel<<<grid, 256>>>(A, B, bias, C, M, N, K, lda, ldb, ldc, sA, sB, sBias, sC);
}

extern "C" void kernel_launch(void* const* d_in, const int* in_sizes, int n_in,
                              void* d_out, int out_size)
{
    (void)in_sizes; (void)n_in; (void)out_size;
    const float* x     = (const float*)d_in[0];
    const int* ei[4]   = {(const int*)d_in[1], (const int*)d_in[2],
                          (const int*)d_in[3], (const int*)d_in[4]};
    const float* Wk1 = (const float*)d_in[5];  const float* bk1 = (const float*)d_in[6];
    const float* Wq1 = (const float*)d_in[7];  const float* bq1 = (const float*)d_in[8];
    const float* Wv1 = (const float*)d_in[9];  const float* bv1 = (const float*)d_in[10];
    const float* Wa1 = (const float*)d_in[11]; const float* ba1 = (const float*)d_in[12];
    const float* arel1 = (const float*)d_in[13];
    const float* mrel1 = (const float*)d_in[14];
    const float* prel1 = (const float*)d_in[15];
    const float* Wk2 = (const float*)d_in[16]; const float* bk2 = (const float*)d_in[17];
    const float* Wq2 = (const float*)d_in[18]; const float* bq2 = (const float*)d_in[19];
    const float* Wv2 = (const float*)d_in[20]; const float* bv2 = (const float*)d_in[21];
    const float* Wa2 = (const float*)d_in[22]; const float* ba2 = (const float*)d_in[23];
    const float* arel2 = (const float*)d_in[24];
    const float* mrel2 = (const float*)d_in[25];
    const float* prel2 = (const float*)d_in[26];
    const float* Wlin = (const float*)d_in[27]; const float* blin = (const float*)d_in[28];
    float* out = (float*)d_out;

    float* S = nullptr;
    cudaGetSymbolAddress((void**)&S, g_scratch);

    float* K1 = S + OFF_K1;  float* Q1 = S + OFF_Q1;  float* V1 = S + OFF_V1;
    float* KR1 = S + OFF_KR1; float* VR1 = S + OFF_VR1;
    float* OUT1 = S + OFF_OUT1; float* ACT1 = S + OFF_ACT1; float* H1 = S + OFF_H1;
    float* K2 = S + OFF_K2;  float* Q2 = S + OFF_Q2;  float* V2 = S + OFF_V2;
    float* KR2 = S + OFF_KR2; float* VR2 = S + OFF_VR2;
    float* OUT2 = S + OFF_OUT2; float* ACT2 = S + OFF_ACT2; float* H2 = S + OFF_H2;
    float* ALPHA = S + OFF_ALPHA;
    float* MB = S + OFF_M;   // unsigned ordered-float max buffer (0 bits == -inf)
    float* SB = S + OFF_S;

    const int st[4] = {0, 0, 1, 1};
    const int dt[4] = {0, 1, 0, 1};

    const int edgewarp_blocks = (EE * NH * 32 + 255) / 256;
    const int edgethr_blocks  = (EE * NH + 255) / 256;

    // ============ LAYER 1 ============
    gemm_tf32(x, Wk1, bk1, K1, NN, F1, F0, F0, F1, F1,
              (size_t)NN * F0, (size_t)F0 * F1, F1, (size_t)NN * F1, TT);
    gemm_tf32(x, Wq1, bq1, Q1, NN, F1, F0, F0, F1, F1,
              (size_t)NN * F0, (size_t)F0 * F1, F1, (size_t)NN * F1, TT);
    gemm_tf32(x, Wv1, bv1, V1, NN, F1, F0, F0, F1, F1,
              (size_t)NN * F0, (size_t)F0 * F1, F1, (size_t)NN * F1, TT);

    for (int e = 0; e < 4; e++) {
        gemm_tf32(K1 + (size_t)st[e] * NN * F1, arel1 + (size_t)e * NH * D1 * D1, nullptr,
                  KR1 + (size_t)e * NN * F1, NN, D1, D1, F1, D1, F1,
                  (size_t)D1, (size_t)D1 * D1, 0, (size_t)D1, NH);
        gemm_tf32(V1 + (size_t)st[e] * NN * F1, mrel1 + (size_t)e * NH * D1 * D1, nullptr,
                  VR1 + (size_t)e * NN * F1, NN, D1, D1, F1, D1, F1,
                  (size_t)D1, (size_t)D1 * D1, 0, (size_t)D1, NH);
    }

    fill_f<<<512, 256>>>(MB, 0.f, 4 * NN * NH);
    fill_f<<<512, 256>>>(SB, 0.f, 4 * NN * NH);
    fill_f<<<2048, 256>>>(OUT1, 0.f, (int)SZ_TNF1);
    {
        float scale = 1.f / sqrtf((float)D1);
        for (int e = 0; e < 4; e++)
            edge_logits<D1><<<edgewarp_blocks, 256>>>(Q1 + (size_t)dt[e] * NN * F1,
                KR1 + (size_t)e * NN * F1, ei[e], ei[e] + EE, prel1 + e * NH,
                ALPHA + (size_t)e * EE * NH, (unsigned*)(MB + (size_t)e * NN * NH), scale, F1);
        for (int e = 0; e < 4; e++)
            edge_expsum<<<edgethr_blocks, 256>>>(ei[e] + EE, ALPHA + (size_t)e * EE * NH,
                (const unsigned*)(MB + (size_t)e * NN * NH), SB + (size_t)e * NN * NH);
        for (int e = 0; e < 4; e++)
            edge_aggregate<D1><<<edgewarp_blocks, 256>>>(VR1 + (size_t)e * NN * F1,
                ei[e], ei[e] + EE, ALPHA + (size_t)e * EE * NH, SB + (size_t)e * NN * NH,
                OUT1 + (size_t)dt[e] * NN * F1, F1);
    }

    gelu_kernel<<<2048, 256>>>(OUT1, ACT1, (int)SZ_TNF1);
    gemm_tf32(ACT1, Wa1, ba1, H1, NN, F1, F1, F1, F1, F1,
              (size_t)NN * F1, (size_t)F1 * F1, F1, (size_t)NN * F1, TT);

    // ============ LAYER 2 ============
    gemm_tf32(H1, Wk2, bk2, K2, NN, F2, F1, F1, F2, F2,
              (size_t)NN * F1, (size_t)F1 * F2, F2, (size_t)NN * F2, TT);
    gemm_tf32(H1, Wq2, bq2, Q2, NN, F2, F1, F1, F2, F2,
              (size_t)NN * F1, (size_t)F1 * F2, F2, (size_t)NN * F2, TT);
    gemm_tf32(H1, Wv2, bv2, V2, NN, F2, F1, F1, F2, F2,
              (size_t)NN * F1, (size_t)F1 * F2, F2, (size_t)NN * F2, TT);

    for (int e = 0; e < 4; e++) {
        gemm_tf32(K2 + (size_t)st[e] * NN * F2, arel2 + (size_t)e * NH * D2 * D2, nullptr,
                  KR2 + (size_t)e * NN * F2, NN, D2, D2, F2, D2, F2,
                  (size_t)D2, (size_t)D2 * D2, 0, (size_t)D2, NH);
        gemm_tf32(V2 + (size_t)st[e] * NN * F2, mrel2 + (size_t)e * NH * D2 * D2, nullptr,
                  VR2 + (size_t)e * NN * F2, NN, D2, D2, F2, D2, F2,
                  (size_t)D2, (size_t)D2 * D2, 0, (size_t)D2, NH);
    }

    fill_f<<<512, 256>>>(MB, 0.f, 4 * NN * NH);
    fill_f<<<512, 256>>>(SB, 0.f, 4 * NN * NH);
    fill_f<<<2048, 256>>>(OUT2, 0.f, (int)SZ_TNF2);
    {
        float scale = 1.f / sqrtf((float)D2);
        for (int e = 0; e < 4; e++)
            edge_logits<D2><<<edgewarp_blocks, 256>>>(Q2 + (size_t)dt[e] * NN * F2,
                KR2 + (size_t)e * NN * F2, ei[e], ei[e] + EE, prel2 + e * NH,
                ALPHA + (size_t)e * EE * NH, (unsigned*)(MB + (size_t)e * NN * NH), scale, F2);
        for (int e = 0; e < 4; e++)
            edge_expsum<<<edgethr_blocks, 256>>>(ei[e] + EE, ALPHA + (size_t)e * EE * NH,
                (const unsigned*)(MB + (size_t)e * NN * NH), SB + (size_t)e * NN * NH);
        for (int e = 0; e < 4; e++)
            edge_aggregate<D2><<<edgewarp_blocks, 256>>>(VR2 + (size_t)e * NN * F2,
                ei[e], ei[e] + EE, ALPHA + (size_t)e * EE * NH, SB + (size_t)e * NN * NH,
                OUT2 + (size_t)dt[e] * NN * F2, F2);
    }

    gelu_kernel<<<2048, 256>>>(OUT2, ACT2, (int)SZ_TNF2);
    gemm_tf32(ACT2, Wa2, ba2, H2, NN, F2, F2, F2, F2, F2,
              (size_t)NN * F2, (size_t)F2 * F2, F2, (size_t)NN * F2, TT);

    // ============ final linear + softmax ============
    final_kernel<<<(TT * NN * 32 + 255) / 256, 256>>>(H2, Wlin, blin, out);
}

// round 3
// speedup vs baseline: 3.8364x; 1.3642x over previous
#include <cuda_runtime.h>
#include <cuda_bf16.h>
#include <math.h>
#include <stdint.h>

// ---------------- problem constants ----------------
#define NN 10000
#define EE 60000
#define TT 2
#define NH 8
#define F0 2048
#define F1 1024
#define D1 128
#define F2 512
#define D2 64
#define OUTF 8

// ---------------- scratch ----------------
#define SZ_TNF1 ((size_t)TT*NN*F1)
#define SZ_TNF2 ((size_t)TT*NN*F2)
#define SZ_ENF1 ((size_t)4*NN*F1)
#define SZ_ENF2 ((size_t)4*NN*F2)

#define OFF_K1   ((size_t)0)
#define OFF_Q1   (OFF_K1 + SZ_TNF1)
#define OFF_V1   (OFF_Q1 + SZ_TNF1)
#define OFF_KR1  (OFF_V1 + SZ_TNF1)
#define OFF_VR1  (OFF_KR1 + SZ_ENF1)
#define OFF_OUT1 (OFF_VR1 + SZ_ENF1)
#define OFF_ACT1 (OFF_OUT1 + SZ_TNF1)
#define OFF_H1   (OFF_ACT1 + SZ_TNF1)
#define OFF_K2   (OFF_H1 + SZ_TNF1)
#define OFF_Q2   (OFF_K2 + SZ_TNF2)
#define OFF_V2   (OFF_Q2 + SZ_TNF2)
#define OFF_KR2  (OFF_V2 + SZ_TNF2)
#define OFF_VR2  (OFF_KR2 + SZ_ENF2)
#define OFF_OUT2 (OFF_VR2 + SZ_ENF2)
#define OFF_ACT2 (OFF_OUT2 + SZ_TNF2)
#define OFF_H2   (OFF_ACT2 + SZ_TNF2)
#define OFF_ALPHA (OFF_H2 + SZ_TNF2)
#define OFF_S    (OFF_ALPHA + (size_t)4*EE*NH)
#define TOTAL_SCRATCH (OFF_S + (size_t)4*NN*NH)

__device__ float g_scratch[TOTAL_SCRATCH];

// ---------------- helpers ----------------
__device__ __forceinline__ void mma_tf32(float& c0, float& c1, float& c2, float& c3,
                                         uint32_t a0, uint32_t a1, uint32_t a2, uint32_t a3,
                                         uint32_t b0, uint32_t b1) {
    asm volatile("mma.sync.aligned.m16n8k8.row.col.f32.tf32.tf32.f32 "
                 "{%0,%1,%2,%3}, {%4,%5,%6,%7}, {%8,%9}, {%0,%1,%2,%3};"
                 : "+f"(c0), "+f"(c1), "+f"(c2), "+f"(c3)
                 : "r"(a0), "r"(a1), "r"(a2), "r"(a3), "r"(b0), "r"(b1));
}
__device__ __forceinline__ uint32_t smem_u32(const void* p) {
    return (uint32_t)__cvta_generic_to_shared(p);
}
__device__ __forceinline__ void cp16(uint32_t dst, const void* src, int sz) {
    asm volatile("cp.async.cg.shared.global [%0], [%1], 16, %2;" :: "r"(dst), "l"(src), "r"(sz));
}
__device__ __forceinline__ void cp_commit() { asm volatile("cp.async.commit_group;"); }
template<int N> __device__ __forceinline__ void cp_wait() {
    asm volatile("cp.async.wait_group %0;" :: "n"(N));
}

// ---------------- fill ----------------
__global__ void fill_f(float* p, float v, int n) {
    int i = blockIdx.x * blockDim.x + threadIdx.x;
    int stride = gridDim.x * blockDim.x;
    for (; i < n; i += stride) p[i] = v;
}

// ---------------- TF32 GEMM, cp.async double-buffered ----------------
// C[z] = A[z] @ B[z] (+ bias[z]); A row-major [M,lda], B row-major [K,ldb].
// Tile 128x128x16, 2 stages. 8 warps: 2(M) x 4(N), warp tile 64x32.
__global__ __launch_bounds__(256, 2)
void gemm_tf32_db(const float* __restrict__ A, const float* __restrict__ B,
                  const float* __restrict__ bias, float* __restrict__ C,
                  int M, int Nn, int K, int lda, int ldb, int ldc,
                  size_t sA, size_t sB, size_t sBias, size_t sC)
{
    __shared__ float As[2][128][20];   // [m][k], stride 20 -> conflict-free quads
    __shared__ float Bs[2][16][136];   // [k][n], stride 136 (≡8 mod 32)

    int z = blockIdx.z;
    A += (size_t)z * sA;
    B += (size_t)z * sB;
    C += (size_t)z * sC;
    if (bias) bias += (size_t)z * sBias;

    int bm = blockIdx.y * 128, bn = blockIdx.x * 128;
    int tid = threadIdx.x;
    int lane = tid & 31;
    int w = tid >> 5;
    int wm = (w & 1) * 64;
    int wn = (w >> 1) * 32;
    int tg = lane & 3;
    int rowg = lane >> 2;

    float acc[4][4][4];
#pragma unroll
    for (int i = 0; i < 4; i++)
#pragma unroll
        for (int j = 0; j < 4; j++)
#pragma unroll
            for (int r = 0; r < 4; r++) acc[i][j][r] = 0.f;

    const int nk = K / 16;

    // tile loaders: A = 128x16 floats (512 float4), B = 16x128 (512 float4), 2 per thread each
#define LOAD_TILES(kt, s)                                                          \
    do {                                                                           \
        _Pragma("unroll")                                                          \
        for (int p = 0; p < 2; p++) {                                              \
            int idx = tid + p * 256;                                               \
            int m = idx >> 2, c4 = (idx & 3) * 4;                                  \
            int gm = bm + m;                                                       \
            const float* srcp = A + (size_t)(gm < M ? gm : M - 1) * lda + (kt) + c4; \
            cp16(smem_u32(&As[s][m][c4]), srcp, gm < M ? 16 : 0);                  \
        }                                                                          \
        _Pragma("unroll")                                                          \
        for (int p = 0; p < 2; p++) {                                              \
            int idx = tid + p * 256;                                               \
            int kr = idx >> 5, c4 = (idx & 31) * 4;                                \
            int gn = bn + c4;                                                      \
            const float* srcp = B + (size_t)((kt) + kr) * ldb + (gn < Nn ? gn : 0); \
            cp16(smem_u32(&Bs[s][kr][c4]), srcp, gn < Nn ? 16 : 0);                \
        }                                                                          \
    } while (0)

    LOAD_TILES(0, 0);
    cp_commit();

    for (int it = 0; it < nk; it++) {
        int cur = it & 1;
        if (it + 1 < nk) {
            LOAD_TILES((it + 1) * 16, cur ^ 1);
            cp_commit();
            cp_wait<1>();
        } else {
            cp_wait<0>();
        }
        __syncthreads();

#pragma unroll
        for (int ks = 0; ks < 2; ks++) {
            int k0 = ks * 8;
            uint32_t af[4][4], bf[4][2];
#pragma unroll
            for (int mt = 0; mt < 4; mt++) {
                int mr = wm + mt * 16 + rowg;
                af[mt][0] = __float_as_uint(As[cur][mr][k0 + tg]);
                af[mt][1] = __float_as_uint(As[cur][mr + 8][k0 + tg]);
                af[mt][2] = __float_as_uint(As[cur][mr][k0 + tg + 4]);
                af[mt][3] = __float_as_uint(As[cur][mr + 8][k0 + tg + 4]);
            }
#pragma unroll
            for (int nt = 0; nt < 4; nt++) {
                int nc = wn + nt * 8 + rowg;
                bf[nt][0] = __float_as_uint(Bs[cur][k0 + tg][nc]);
                bf[nt][1] = __float_as_uint(Bs[cur][k0 + tg + 4][nc]);
            }
#pragma unroll
            for (int mt = 0; mt < 4; mt++)
#pragma unroll
                for (int nt = 0; nt < 4; nt++)
                    mma_tf32(acc[mt][nt][0], acc[mt][nt][1], acc[mt][nt][2], acc[mt][nt][3],
                             af[mt][0], af[mt][1], af[mt][2], af[mt][3],
                             bf[nt][0], bf[nt][1]);
        }
        __syncthreads();
    }
#undef LOAD_TILES

    // ---- epilogue ----
#pragma unroll
    for (int mt = 0; mt < 4; mt++) {
#pragma unroll
        for (int nt = 0; nt < 4; nt++) {
            int gm0 = bm + wm + mt * 16 + rowg;
            int gn0 = bn + wn + nt * 8 + tg * 2;
            float b0 = 0.f, b1 = 0.f;
            if (bias) {
                if (gn0 < Nn) b0 = bias[gn0];
                if (gn0 + 1 < Nn) b1 = bias[gn0 + 1];
            }
            if (gm0 < M) {
                if (gn0 < Nn)     C[(size_t)gm0 * ldc + gn0]     = acc[mt][nt][0] + b0;
                if (gn0 + 1 < Nn) C[(size_t)gm0 * ldc + gn0 + 1] = acc[mt][nt][1] + b1;
            }
            if (gm0 + 8 < M) {
                if (gn0 < Nn)     C[(size_t)(gm0 + 8) * ldc + gn0]     = acc[mt][nt][2] + b0;
                if (gn0 + 1 < Nn) C[(size_t)(gm0 + 8) * ldc + gn0 + 1] = acc[mt][nt][3] + b1;
            }
        }
    }
}

// ---------------- edge kernels ----------------
// warp per (edge, head): exp(logit) + atomic sum (no max pass: |logit| << 80)
template<int D>
__global__ void edge_logits(const float* __restrict__ q, const float* __restrict__ kr,
                            const int* __restrict__ src, const int* __restrict__ dst,
                            const float* __restrict__ prel_row,
                            float* __restrict__ alpha, float* __restrict__ sbuf,
                            float scale, int F)
{
    int warp = (blockIdx.x * blockDim.x + threadIdx.x) >> 5;
    int lane = threadIdx.x & 31;
    if (warp >= EE * NH) return;
    int e = warp / NH, h = warp % NH;
    int sN = src[e], dN = dst[e];
    const float* qp = q + (size_t)dN * F + h * D;
    const float* kp = kr + (size_t)sN * F + h * D;
    float acc = 0.f;
    if (D == 128) {
        float4 a = *(const float4*)(qp + lane * 4);
        float4 b = *(const float4*)(kp + lane * 4);
        acc = a.x * b.x + a.y * b.y + a.z * b.z + a.w * b.w;
    } else {
        float2 a = *(const float2*)(qp + lane * 2);
        float2 b = *(const float2*)(kp + lane * 2);
        acc = a.x * b.x + a.y * b.y;
    }
#pragma unroll
    for (int o = 16; o; o >>= 1) acc += __shfl_down_sync(0xFFFFFFFFu, acc, o);
    if (lane == 0) {
        float ex = expf(acc * prel_row[h] * scale);
        alpha[(size_t)e * NH + h] = ex;
        atomicAdd(&sbuf[(size_t)dN * NH + h], ex);
    }
}

// warp per (edge, head): normalized weight * v_rel scatter-add (vector atomics)
template<int D>
__global__ void edge_aggregate(const float* __restrict__ vr,
                               const int* __restrict__ src, const int* __restrict__ dst,
                               const float* __restrict__ alpha, const float* __restrict__ sbuf,
                               float* __restrict__ out, int F)
{
    int warp = (blockIdx.x * blockDim.x + threadIdx.x) >> 5;
    int lane = threadIdx.x & 31;
    if (warp >= EE * NH) return;
    int e = warp / NH, h = warp % NH;
    int sN = src[e], dN = dst[e];
    float wgt = alpha[(size_t)e * NH + h] / (sbuf[(size_t)dN * NH + h] + 1e-16f);
    const float* vp = vr + (size_t)sN * F + h * D;
    float* op = out + (size_t)dN * F + h * D;
    if (D == 128) {
        float4 v = *(const float4*)(vp + lane * 4);
        atomicAdd((float4*)(op + lane * 4),
                  make_float4(v.x * wgt, v.y * wgt, v.z * wgt, v.w * wgt));
    } else {
        float2 v = *(const float2*)(vp + lane * 2);
        atomicAdd((float2*)(op + lane * 2), make_float2(v.x * wgt, v.y * wgt));
    }
}

// ---------------- gelu ----------------
__global__ void gelu_kernel(const float* __restrict__ in, float* __restrict__ out, int n)
{
    int i = (blockIdx.x * blockDim.x + threadIdx.x) * 4;
    int stride = gridDim.x * blockDim.x * 4;
    for (; i < n; i += stride) {
        float4 x = *(const float4*)(in + i);
        float4 r;
        r.x = 0.5f * x.x * (1.0f + erff(x.x * 0.70710678118654752440f));
        r.y = 0.5f * x.y * (1.0f + erff(x.y * 0.70710678118654752440f));
        r.z = 0.5f * x.z * (1.0f + erff(x.z * 0.70710678118654752440f));
        r.w = 0.5f * x.w * (1.0f + erff(x.w * 0.70710678118654752440f));
        *(float4*)(out + i) = r;
    }
}

// ---------------- final linear + row softmax ----------------
__global__ void final_kernel(const float* __restrict__ h2, const float* __restrict__ W,
                             const float* __restrict__ b, float* __restrict__ out)
{
    int warp = (blockIdx.x * blockDim.x + threadIdx.x) >> 5;
    int lane = threadIdx.x & 31;
    if (warp >= TT * NN) return;
    const float* hp = h2 + (size_t)warp * F2;
    float acc[OUTF];
#pragma unroll
    for (int o = 0; o < OUTF; o++) acc[o] = 0.f;
    for (int f = lane; f < F2; f += 32) {
        float xv = hp[f];
        const float* wp = W + (size_t)f * OUTF;
#pragma unroll
        for (int o = 0; o < OUTF; o++) acc[o] = fmaf(xv, wp[o], acc[o]);
    }
#pragma unroll
    for (int o = 0; o < OUTF; o++) {
#pragma unroll
        for (int off = 16; off; off >>= 1) acc[o] += __shfl_down_sync(0xFFFFFFFFu, acc[o], off);
    }
    if (lane == 0) {
        float l[OUTF];
        float m = -1e30f;
#pragma unroll
        for (int o = 0; o < OUTF; o++) { l[o] = acc[o] + b[o]; m = fmaxf(m, l[o]); }
        float s = 0.f;
#pragma unroll
        for (int o = 0; o < OUTF; o++) { l[o] = expf(l[o] - m); s += l[o]; }
        float inv = 1.f / s;
        float* op = out + (size_t)warp * OUTF;
#pragma unroll
        for (int o = 0; o < OUTF; o++) op[o] = l[o] * inv;
    }
}

// ---------------- host-side launch helper ----------------
static void gemm_tf32(const float* A, const float* B, const float* bias, float* C,
                      int M, int N, int K, int lda, int ldb, int ldc,
                      size_t sA, size_t sB, size_t sBias, size_t sC, int batch)
{
    dim3 grid((N + 127) / 128, (M + 127) / 128, batch);
    gemm_tf32_db<<<grid, 256>>>(A, B, bias, C, M, N, K, lda, ldb, ldc, sA, sB, sBias, sC);
}

extern "C" void kernel_launch(void* const* d_in, const int* in_sizes, int n_in,
                              void* d_out, int out_size)
{
    (void)in_sizes; (void)n_in; (void)out_size;
    const float* x     = (const float*)d_in[0];
    const int* ei[4]   = {(const int*)d_in[1], (const int*)d_in[2],
                          (const int*)d_in[3], (const int*)d_in[4]};
    const float* Wk1 = (const float*)d_in[5];  const float* bk1 = (const float*)d_in[6];
    const float* Wq1 = (const float*)d_in[7];  const float* bq1 = (const float*)d_in[8];
    const float* Wv1 = (const float*)d_in[9];  const float* bv1 = (const float*)d_in[10];
    const float* Wa1 = (const float*)d_in[11]; const float* ba1 = (const float*)d_in[12];
    const float* arel1 = (const float*)d_in[13];
    const float* mrel1 = (const float*)d_in[14];
    const float* prel1 = (const float*)d_in[15];
    const float* Wk2 = (const float*)d_in[16]; const float* bk2 = (const float*)d_in[17];
    const float* Wq2 = (const float*)d_in[18]; const float* bq2 = (const float*)d_in[19];
    const float* Wv2 = (const float*)d_in[20]; const float* bv2 = (const float*)d_in[21];
    const float* Wa2 = (const float*)d_in[22]; const float* ba2 = (const float*)d_in[23];
    const float* arel2 = (const float*)d_in[24];
    const float* mrel2 = (const float*)d_in[25];
    const float* prel2 = (const float*)d_in[26];
    const float* Wlin = (const float*)d_in[27]; const float* blin = (const float*)d_in[28];
    float* out = (float*)d_out;

    float* S = nullptr;
    cudaGetSymbolAddress((void**)&S, g_scratch);

    float* K1 = S + OFF_K1;  float* Q1 = S + OFF_Q1;  float* V1 = S + OFF_V1;
    float* KR1 = S + OFF_KR1; float* VR1 = S + OFF_VR1;
    float* OUT1 = S + OFF_OUT1; float* ACT1 = S + OFF_ACT1; float* H1 = S + OFF_H1;
    float* K2 = S + OFF_K2;  float* Q2 = S + OFF_Q2;  float* V2 = S + OFF_V2;
    float* KR2 = S + OFF_KR2; float* VR2 = S + OFF_VR2;
    float* OUT2 = S + OFF_OUT2; float* ACT2 = S + OFF_ACT2; float* H2 = S + OFF_H2;
    float* ALPHA = S + OFF_ALPHA;
    float* SB = S + OFF_S;

    const int st[4] = {0, 0, 1, 1};
    const int dt[4] = {0, 1, 0, 1};

    const int edgewarp_blocks = (EE * NH * 32 + 255) / 256;

    // ============ LAYER 1 ============
    gemm_tf32(x, Wk1, bk1, K1, NN, F1, F0, F0, F1, F1,
              (size_t)NN * F0, (size_t)F0 * F1, F1, (size_t)NN * F1, TT);
    gemm_tf32(x, Wq1, bq1, Q1, NN, F1, F0, F0, F1, F1,
              (size_t)NN * F0, (size_t)F0 * F1, F1, (size_t)NN * F1, TT);
    gemm_tf32(x, Wv1, bv1, V1, NN, F1, F0, F0, F1, F1,
              (size_t)NN * F0, (size_t)F0 * F1, F1, (size_t)NN * F1, TT);

    for (int e = 0; e < 4; e++) {
        gemm_tf32(K1 + (size_t)st[e] * NN * F1, arel1 + (size_t)e * NH * D1 * D1, nullptr,
                  KR1 + (size_t)e * NN * F1, NN, D1, D1, F1, D1, F1,
                  (size_t)D1, (size_t)D1 * D1, 0, (size_t)D1, NH);
        gemm_tf32(V1 + (size_t)st[e] * NN * F1, mrel1 + (size_t)e * NH * D1 * D1, nullptr,
                  VR1 + (size_t)e * NN * F1, NN, D1, D1, F1, D1, F1,
                  (size_t)D1, (size_t)D1 * D1, 0, (size_t)D1, NH);
    }

    fill_f<<<512, 256>>>(SB, 0.f, 4 * NN * NH);
    fill_f<<<2048, 256>>>(OUT1, 0.f, (int)SZ_TNF1);
    {
        float scale = 1.f / sqrtf((float)D1);
        for (int e = 0; e < 4; e++)
            edge_logits<D1><<<edgewarp_blocks, 256>>>(Q1 + (size_t)dt[e] * NN * F1,
                KR1 + (size_t)e * NN * F1, ei[e], ei[e] + EE, prel1 + e * NH,
                ALPHA + (size_t)e * EE * NH, SB + (size_t)e * NN * NH, scale, F1);
        for (int e = 0; e < 4; e++)
            edge_aggregate<D1><<<edgewarp_blocks, 256>>>(VR1 + (size_t)e * NN * F1,
                ei[e], ei[e] + EE, ALPHA + (size_t)e * EE * NH, SB + (size_t)e * NN * NH,
                OUT1 + (size_t)dt[e] * NN * F1, F1);
    }

    gelu_kernel<<<2048, 256>>>(OUT1, ACT1, (int)SZ_TNF1);
    gemm_tf32(ACT1, Wa1, ba1, H1, NN, F1, F1, F1, F1, F1,
              (size_t)NN * F1, (size_t)F1 * F1, F1, (size_t)NN * F1, TT);

    // ============ LAYER 2 ============
    gemm_tf32(H1, Wk2, bk2, K2, NN, F2, F1, F1, F2, F2,
              (size_t)NN * F1, (size_t)F1 * F2, F2, (size_t)NN * F2, TT);
    gemm_tf32(H1, Wq2, bq2, Q2, NN, F2, F1, F1, F2, F2,
              (size_t)NN * F1, (size_t)F1 * F2, F2, (size_t)NN * F2, TT);
    gemm_tf32(H1, Wv2, bv2, V2, NN, F2, F1, F1, F2, F2,
              (size_t)NN * F1, (size_t)F1 * F2, F2, (size_t)NN * F2, TT);

    for (int e = 0; e < 4; e++) {
        gemm_tf32(K2 + (size_t)st[e] * NN * F2, arel2 + (size_t)e * NH * D2 * D2, nullptr,
                  KR2 + (size_t)e * NN * F2, NN, D2, D2, F2, D2, F2,
                  (size_t)D2, (size_t)D2 * D2, 0, (size_t)D2, NH);
        gemm_tf32(V2 + (size_t)st[e] * NN * F2, mrel2 + (size_t)e * NH * D2 * D2, nullptr,
                  VR2 + (size_t)e * NN * F2, NN, D2, D2, F2, D2, F2,
                  (size_t)D2, (size_t)D2 * D2, 0, (size_t)D2, NH);
    }

    fill_f<<<512, 256>>>(SB, 0.f, 4 * NN * NH);
    fill_f<<<2048, 256>>>(OUT2, 0.f, (int)SZ_TNF2);
    {
        float scale = 1.f / sqrtf((float)D2);
        for (int e = 0; e < 4; e++)
            edge_logits<D2><<<edgewarp_blocks, 256>>>(Q2 + (size_t)dt[e] * NN * F2,
                KR2 + (size_t)e * NN * F2, ei[e], ei[e] + EE, prel2 + e * NH,
                ALPHA + (size_t)e * EE * NH, SB + (size_t)e * NN * NH, scale, F2);
        for (int e = 0; e < 4; e++)
            edge_aggregate<D2><<<edgewarp_blocks, 256>>>(VR2 + (size_t)e * NN * F2,
                ei[e], ei[e] + EE, ALPHA + (size_t)e * EE * NH, SB + (size_t)e * NN * NH,
                OUT2 + (size_t)dt[e] * NN * F2, F2);
    }

    gelu_kernel<<<2048, 256>>>(OUT2, ACT2, (int)SZ_TNF2);
    gemm_tf32(ACT2, Wa2, ba2, H2, NN, F2, F2, F2, F2, F2,
              (size_t)NN * F2, (size_t)F2 * F2, F2, (size_t)NN * F2, TT);

    // ============ final ============
    final_kernel<<<(TT * NN * 32 + 255) / 256, 256>>>(H2, Wlin, blin, out);
}

// round 8
// speedup vs baseline: 6.1154x; 1.5941x over previous
#include <cuda_runtime.h>
#include <cuda_bf16.h>
#include <math.h>
#include <stdint.h>

// ---------------- problem constants ----------------
#define NN 10000
#define EE 60000
#define TT 2
#define NH 8
#define F0 2048
#define F1 1024
#define D1 128
#define F2 512
#define D2 64
#define OUTF 8

typedef __nv_bfloat16 bf16;
typedef __nv_bfloat162 bf162;

// ---------------- bf16 scratch offsets (elements) ----------------
#define OB_XB      ((size_t)0)                               // TT*NN*F0
#define OB_WKQV1   (OB_XB + (size_t)TT*NN*F0)                // TT*F0*3F1
#define OB_WA1     (OB_WKQV1 + (size_t)TT*F0*3*F1)
#define OB_AREL1   (OB_WA1 + (size_t)TT*F1*F1)
#define OB_MREL1   (OB_AREL1 + (size_t)4*NH*D1*D1)
#define OB_WKQV2   (OB_MREL1 + (size_t)4*NH*D1*D1)
#define OB_WA2     (OB_WKQV2 + (size_t)TT*F1*3*F2)
#define OB_AREL2   (OB_WA2 + (size_t)TT*F2*F2)
#define OB_MREL2   (OB_AREL2 + (size_t)4*NH*D2*D2)
#define OB_KQV1    (OB_MREL2 + (size_t)4*NH*D2*D2)           // TT*NN*3F1
#define OB_KR1     (OB_KQV1 + (size_t)TT*NN*3*F1)            // 4*NN*F1
#define OB_VR1     (OB_KR1 + (size_t)4*NN*F1)
#define OB_ACT1    (OB_VR1 + (size_t)4*NN*F1)                // TT*NN*F1
#define OB_H1      (OB_ACT1 + (size_t)TT*NN*F1)
#define OB_KQV2    (OB_H1 + (size_t)TT*NN*F1)                // TT*NN*3F2
#define OB_KR2     (OB_KQV2 + (size_t)TT*NN*3*F2)
#define OB_VR2     (OB_KR2 + (size_t)4*NN*F2)
#define OB_ACT2    (OB_VR2 + (size_t)4*NN*F2)
#define OB_H2      (OB_ACT2 + (size_t)TT*NN*F2)
#define OB_TOTAL   (OB_H2 + (size_t)TT*NN*F2)

__device__ bf16 g_bf[OB_TOTAL];

// ---------------- fp32 scratch ----------------
#define OF_OUT1   ((size_t)0)                                // TT*NN*F1
#define OF_OUT2   (OF_OUT1 + (size_t)TT*NN*F1)               // TT*NN*F2
#define OF_ALPHA  (OF_OUT2 + (size_t)TT*NN*F2)               // 4*EE*NH
#define OF_SB     (OF_ALPHA + (size_t)4*EE*NH)               // 4*NN*NH
#define OF_BKQV1  (OF_SB + (size_t)4*NN*NH)                  // TT*3F1
#define OF_BKQV2  (OF_BKQV1 + (size_t)TT*3*F1)               // TT*3F2
#define OF_TOTAL  (OF_BKQV2 + (size_t)TT*3*F2)

__device__ float g_f32[OF_TOTAL];

// ---------------- asm helpers ----------------
__device__ __forceinline__ uint32_t smem_u32(const void* p) {
    return (uint32_t)__cvta_generic_to_shared(p);
}
__device__ __forceinline__ void cp16(uint32_t dst, const void* src, int sz) {
    asm volatile("cp.async.cg.shared.global [%0], [%1], 16, %2;" :: "r"(dst), "l"(src), "r"(sz));
}
__device__ __forceinline__ void cp_commit() { asm volatile("cp.async.commit_group;"); }
template<int N> __device__ __forceinline__ void cp_wait() {
    asm volatile("cp.async.wait_group %0;" :: "n"(N));
}
__device__ __forceinline__ void ldsm4(uint32_t& r0, uint32_t& r1, uint32_t& r2, uint32_t& r3, uint32_t a) {
    asm volatile("ldmatrix.sync.aligned.m8n8.x4.shared.b16 {%0,%1,%2,%3}, [%4];"
                 : "=r"(r0), "=r"(r1), "=r"(r2), "=r"(r3) : "r"(a));
}
__device__ __forceinline__ void ldsm4t(uint32_t& r0, uint32_t& r1, uint32_t& r2, uint32_t& r3, uint32_t a) {
    asm volatile("ldmatrix.sync.aligned.m8n8.x4.trans.shared.b16 {%0,%1,%2,%3}, [%4];"
                 : "=r"(r0), "=r"(r1), "=r"(r2), "=r"(r3) : "r"(a));
}
__device__ __forceinline__ void mma_bf16(float* c, const uint32_t* a, const uint32_t* b) {
    asm volatile("mma.sync.aligned.m16n8k16.row.col.f32.bf16.bf16.f32 "
                 "{%0,%1,%2,%3}, {%4,%5,%6,%7}, {%8,%9}, {%0,%1,%2,%3};"
                 : "+f"(c[0]), "+f"(c[1]), "+f"(c[2]), "+f"(c[3])
                 : "r"(a[0]), "r"(a[1]), "r"(a[2]), "r"(a[3]), "r"(b[0]), "r"(b[1]));
}

// ---------------- conversion / pack kernels ----------------
__global__ void cvt_bf4(const float* __restrict__ in, bf16* __restrict__ out, size_t n4) {
    size_t stride = (size_t)gridDim.x * blockDim.x;
    for (size_t i = (size_t)blockIdx.x * blockDim.x + threadIdx.x; i < n4; i += stride) {
        float4 v = ((const float4*)in)[i];
        bf162 a, b;
        a.x = __float2bfloat16(v.x); a.y = __float2bfloat16(v.y);
        b.x = __float2bfloat16(v.z); b.y = __float2bfloat16(v.w);
        ((bf162*)out)[i * 2] = a;
        ((bf162*)out)[i * 2 + 1] = b;
    }
}

// pack 3 weight matrices [T,Kd,Fo] along N -> out [T,Kd,3*Fo] bf16
__global__ void pack3w(const float* __restrict__ Wk, const float* __restrict__ Wq,
                       const float* __restrict__ Wv, bf16* __restrict__ out, int Kd, int Fo) {
    size_t total4 = (size_t)TT * Kd * 3 * Fo / 4;
    size_t stride = (size_t)gridDim.x * blockDim.x;
    for (size_t i = (size_t)blockIdx.x * blockDim.x + threadIdx.x; i < total4; i += stride) {
        size_t idx = i * 4;
        int j = (int)(idx % (size_t)(3 * Fo));
        size_t tk = idx / (size_t)(3 * Fo);
        int m = j / Fo, c = j % Fo;
        const float* W = (m == 0) ? Wk : ((m == 1) ? Wq : Wv);
        float4 v = *(const float4*)(W + tk * Fo + c);
        bf162 a, b;
        a.x = __float2bfloat16(v.x); a.y = __float2bfloat16(v.y);
        b.x = __float2bfloat16(v.z); b.y = __float2bfloat16(v.w);
        bf162* o = (bf162*)(out + idx);
        o[0] = a; o[1] = b;
    }
}

__global__ void pack3b(const float* __restrict__ bk, const float* __restrict__ bq,
                       const float* __restrict__ bv, float* __restrict__ out, int Fo) {
    int total = TT * 3 * Fo;
    for (int i = blockIdx.x * blockDim.x + threadIdx.x; i < total; i += gridDim.x * blockDim.x) {
        int j = i % (3 * Fo), t = i / (3 * Fo);
        int m = j / Fo, c = j % Fo;
        const float* b = (m == 0) ? bk : ((m == 1) ? bq : bv);
        out[i] = b[t * Fo + c];
    }
}

__global__ void fill_f(float* p, float v, int n) {
    int i = blockIdx.x * blockDim.x + threadIdx.x;
    int stride = gridDim.x * blockDim.x;
    for (; i < n; i += stride) p[i] = v;
}

// ---------------- bf16 tensor-core GEMM, 3-stage cp.async + ldmatrix ----------------
// C[z](bf16) = A[z](bf16)[M,lda] @ B[z](bf16)[K,ldb] + bias[z](fp32)
// Tile 128x128x32; 8 warps: 2(M) x 4(N); warp tile 64x32.
#define GSTAGES 3
#define GSMEM_BYTES (GSTAGES * (128 * 40 + 32 * 136) * 2)

__global__ __launch_bounds__(256, 2)
void gemm_bf(const bf16* __restrict__ A, const bf16* __restrict__ B,
             const float* __restrict__ bias, bf16* __restrict__ C,
             int M, int Nn, int K, int lda, int ldb, int ldc,
             size_t sA, size_t sB, size_t sBias, size_t sC)
{
    extern __shared__ char dynsmem[];
    bf16 (*As)[128][40] = (bf16(*)[128][40])dynsmem;
    bf16 (*Bs)[32][136] = (bf16(*)[32][136])(dynsmem + GSTAGES * 128 * 40 * 2);

    int z = blockIdx.z;
    A += (size_t)z * sA;
    B += (size_t)z * sB;
    C += (size_t)z * sC;
    if (bias) bias += (size_t)z * sBias;

    int bm = blockIdx.y * 128, bn = blockIdx.x * 128;
    int tid = threadIdx.x;
    int lane = tid & 31;
    int w = tid >> 5;
    int wm = (w & 1) * 64;
    int wn = (w >> 1) * 32;
    int tg = lane & 3;
    int rowg = lane >> 2;

    float acc[4][4][4];
#pragma unroll
    for (int i = 0; i < 4; i++)
#pragma unroll
        for (int j = 0; j < 4; j++)
#pragma unroll
            for (int r = 0; r < 4; r++) acc[i][j][r] = 0.f;

    const int nk = K / 32;

#define GLOAD(kt, s)                                                                   \
    do {                                                                               \
        _Pragma("unroll")                                                              \
        for (int p = 0; p < 2; p++) {                                                  \
            int idx = tid + p * 256;                                                   \
            int m = idx >> 2, c = (idx & 3) * 8;                                       \
            int gm = bm + m;                                                           \
            const bf16* sp = A + (size_t)(gm < M ? gm : 0) * lda + (kt) + c;           \
            cp16(smem_u32(&As[s][m][c]), sp, gm < M ? 16 : 0);                         \
        }                                                                              \
        _Pragma("unroll")                                                              \
        for (int p = 0; p < 2; p++) {                                                  \
            int idx = tid + p * 256;                                                   \
            int kr = idx >> 4, c = (idx & 15) * 8;                                     \
            int gn = bn + c;                                                           \
            const bf16* sp = B + (size_t)((kt) + kr) * ldb + (gn < Nn ? gn : 0);       \
            cp16(smem_u32(&Bs[s][kr][c]), sp, gn < Nn ? 16 : 0);                       \
        }                                                                              \
    } while (0)

#pragma unroll
    for (int s = 0; s < GSTAGES - 1; s++) {
        if (s < nk) GLOAD(s * 32, s);
        cp_commit();
    }

    for (int it = 0; it < nk; it++) {
        cp_wait<GSTAGES - 2>();
        __syncthreads();
        int nxt = it + GSTAGES - 1;
        int slot = nxt % GSTAGES;
        if (nxt < nk) GLOAD(nxt * 32, slot);
        cp_commit();

        int cur = it % GSTAGES;
#pragma unroll
        for (int ks = 0; ks < 2; ks++) {
            int k0 = ks * 16;
            uint32_t af[4][4], bfr[4][2];
#pragma unroll
            for (int mt = 0; mt < 4; mt++) {
                int row = wm + mt * 16 + (lane & 15);
                int coff = k0 + ((lane >> 4) << 3);
                ldsm4(af[mt][0], af[mt][1], af[mt][2], af[mt][3],
                      smem_u32(&As[cur][row][coff]));
            }
#pragma unroll
            for (int ntp = 0; ntp < 2; ntp++) {
                int row = k0 + (lane & 7) + ((lane >> 3) & 1) * 8;
                int col = wn + ntp * 16 + ((lane >> 4) << 3);
                uint32_t r0, r1, r2, r3;
                ldsm4t(r0, r1, r2, r3, smem_u32(&Bs[cur][row][col]));
                bfr[ntp * 2][0] = r0; bfr[ntp * 2][1] = r1;
                bfr[ntp * 2 + 1][0] = r2; bfr[ntp * 2 + 1][1] = r3;
            }
#pragma unroll
            for (int mt = 0; mt < 4; mt++)
#pragma unroll
                for (int nt = 0; nt < 4; nt++)
                    mma_bf16(acc[mt][nt], af[mt], bfr[nt]);
        }
    }
#undef GLOAD

    // epilogue: +bias, convert to bf16
#pragma unroll
    for (int mt = 0; mt < 4; mt++) {
#pragma unroll
        for (int nt = 0; nt < 4; nt++) {
            int gm0 = bm + wm + mt * 16 + rowg;
            int gn0 = bn + wn + nt * 8 + tg * 2;
            if (gn0 >= Nn) continue;
            float b0 = 0.f, b1 = 0.f;
            if (bias) { b0 = bias[gn0]; b1 = bias[gn0 + 1]; }
            if (gm0 < M) {
                bf162 v;
                v.x = __float2bfloat16(acc[mt][nt][0] + b0);
                v.y = __float2bfloat16(acc[mt][nt][1] + b1);
                *(bf162*)(C + (size_t)gm0 * ldc + gn0) = v;
            }
            if (gm0 + 8 < M) {
                bf162 v;
                v.x = __float2bfloat16(acc[mt][nt][2] + b0);
                v.y = __float2bfloat16(acc[mt][nt][3] + b1);
                *(bf162*)(C + (size_t)(gm0 + 8) * ldc + gn0) = v;
            }
        }
    }
}

// ---------------- edge kernels (bf16 inputs) ----------------
template<int D>
__global__ void edge_logits(const bf16* __restrict__ q, int ldq,
                            const bf16* __restrict__ kr, int ldk,
                            const int* __restrict__ src, const int* __restrict__ dst,
                            const float* __restrict__ prel_row,
                            float* __restrict__ alpha, float* __restrict__ sbuf, float scale)
{
    int warp = (blockIdx.x * blockDim.x + threadIdx.x) >> 5;
    int lane = threadIdx.x & 31;
    if (warp >= EE * NH) return;
    int e = warp / NH, h = warp % NH;
    int sN = src[e], dN = dst[e];
    const bf162* qp = (const bf162*)(q + (size_t)dN * ldq + h * D);
    const bf162* kp = (const bf162*)(kr + (size_t)sN * ldk + h * D);
    float acc = 0.f;
    if (D == 128) {
        float2 a0 = __bfloat1622float2(qp[lane * 2]);
        float2 a1 = __bfloat1622float2(qp[lane * 2 + 1]);
        float2 b0 = __bfloat1622float2(kp[lane * 2]);
        float2 b1 = __bfloat1622float2(kp[lane * 2 + 1]);
        acc = a0.x * b0.x + a0.y * b0.y + a1.x * b1.x + a1.y * b1.y;
    } else {
        float2 a = __bfloat1622float2(qp[lane]);
        float2 b = __bfloat1622float2(kp[lane]);
        acc = a.x * b.x + a.y * b.y;
    }
#pragma unroll
    for (int o = 16; o; o >>= 1) acc += __shfl_down_sync(0xFFFFFFFFu, acc, o);
    if (lane == 0) {
        float ex = expf(acc * prel_row[h] * scale);
        alpha[(size_t)e * NH + h] = ex;
        atomicAdd(&sbuf[(size_t)dN * NH + h], ex);
    }
}

template<int D>
__global__ void edge_aggregate(const bf16* __restrict__ vr, int ldv,
                               const int* __restrict__ src, const int* __restrict__ dst,
                               const float* __restrict__ alpha, const float* __restrict__ sbuf,
                               float* __restrict__ out, int ldo)
{
    int warp = (blockIdx.x * blockDim.x + threadIdx.x) >> 5;
    int lane = threadIdx.x & 31;
    if (warp >= EE * NH) return;
    int e = warp / NH, h = warp % NH;
    int sN = src[e], dN = dst[e];
    float wgt = alpha[(size_t)e * NH + h] / (sbuf[(size_t)dN * NH + h] + 1e-16f);
    const bf162* vp = (const bf162*)(vr + (size_t)sN * ldv + h * D);
    float* op = out + (size_t)dN * ldo + h * D;
    if (D == 128) {
        float2 v0 = __bfloat1622float2(vp[lane * 2]);
        float2 v1 = __bfloat1622float2(vp[lane * 2 + 1]);
        atomicAdd((float4*)(op + lane * 4),
                  make_float4(v0.x * wgt, v0.y * wgt, v1.x * wgt, v1.y * wgt));
    } else {
        float2 v = __bfloat1622float2(vp[lane]);
        atomicAdd((float2*)(op + lane * 2), make_float2(v.x * wgt, v.y * wgt));
    }
}

// ---------------- gelu: fp32 in -> bf16 out ----------------
__global__ void gelu_bf(const float* __restrict__ in, bf16* __restrict__ out, int n)
{
    int i = (blockIdx.x * blockDim.x + threadIdx.x) * 4;
    int stride = gridDim.x * blockDim.x * 4;
    for (; i < n; i += stride) {
        float4 x = *(const float4*)(in + i);
        bf162 a, b;
        a.x = __float2bfloat16(0.5f * x.x * (1.0f + erff(x.x * 0.70710678f)));
        a.y = __float2bfloat16(0.5f * x.y * (1.0f + erff(x.y * 0.70710678f)));
        b.x = __float2bfloat16(0.5f * x.z * (1.0f + erff(x.z * 0.70710678f)));
        b.y = __float2bfloat16(0.5f * x.w * (1.0f + erff(x.w * 0.70710678f)));
        ((bf162*)(out + i))[0] = a;
        ((bf162*)(out + i))[1] = b;
    }
}

// ---------------- final linear + row softmax (bf16 h2) ----------------
__global__ void final_kernel(const bf16* __restrict__ h2, const float* __restrict__ W,
                             const float* __restrict__ b, float* __restrict__ out)
{
    int warp = (blockIdx.x * blockDim.x + threadIdx.x) >> 5;
    int lane = threadIdx.x & 31;
    if (warp >= TT * NN) return;
    const bf16* hp = h2 + (size_t)warp * F2;
    float acc[OUTF];
#pragma unroll
    for (int o = 0; o < OUTF; o++) acc[o] = 0.f;
    for (int f = lane; f < F2; f += 32) {
        float xv = __bfloat162float(hp[f]);
        const float* wp = W + (size_t)f * OUTF;
#pragma unroll
        for (int o = 0; o < OUTF; o++) acc[o] = fmaf(xv, wp[o], acc[o]);
    }
#pragma unroll
    for (int o = 0; o < OUTF; o++) {
#pragma unroll
        for (int off = 16; off; off >>= 1) acc[o] += __shfl_down_sync(0xFFFFFFFFu, acc[o], off);
    }
    if (lane == 0) {
        float l[OUTF];
        float m = -1e30f;
#pragma unroll
        for (int o = 0; o < OUTF; o++) { l[o] = acc[o] + b[o]; m = fmaxf(m, l[o]); }
        float s = 0.f;
#pragma unroll
        for (int o = 0; o < OUTF; o++) { l[o] = expf(l[o] - m); s += l[o]; }
        float inv = 1.f / s;
        float* op = out + (size_t)warp * OUTF;
#pragma unroll
        for (int o = 0; o < OUTF; o++) op[o] = l[o] * inv;
    }
}

// ---------------- host launch helper ----------------
static void gemm(const bf16* A, const bf16* B, const float* bias, bf16* C,
                 int M, int N, int K, int lda, int ldb, int ldc,
                 size_t sA, size_t sB, size_t sBias, size_t sC, int batch)
{
    dim3 grid((N + 127) / 128, (M + 127) / 128, batch);
    gemm_bf<<<grid, 256, GSMEM_BYTES>>>(A, B, bias, C, M, N, K, lda, ldb, ldc, sA, sB, sBias, sC);
}

extern "C" void kernel_launch(void* const* d_in, const int* in_sizes, int n_in,
                              void* d_out, int out_size)
{
    (void)in_sizes; (void)n_in; (void)out_size;
    const float* x     = (const float*)d_in[0];
    const int* ei[4]   = {(const int*)d_in[1], (const int*)d_in[2],
                          (const int*)d_in[3], (const int*)d_in[4]};
    const float* Wk1 = (const float*)d_in[5];  const float* bk1 = (const float*)d_in[6];
    const float* Wq1 = (const float*)d_in[7];  const float* bq1 = (const float*)d_in[8];
    const float* Wv1 = (const float*)d_in[9];  const float* bv1 = (const float*)d_in[10];
    const float* Wa1 = (const float*)d_in[11]; const float* ba1 = (const float*)d_in[12];
    const float* arel1 = (const float*)d_in[13];
    const float* mrel1 = (const float*)d_in[14];
    const float* prel1 = (const float*)d_in[15];
    const float* Wk2 = (const float*)d_in[16]; const float* bk2 = (const float*)d_in[17];
    const float* Wq2 = (const float*)d_in[18]; const float* bq2 = (const float*)d_in[19];
    const float* Wv2 = (const float*)d_in[20]; const float* bv2 = (const float*)d_in[21];
    const float* Wa2 = (const float*)d_in[22]; const float* ba2 = (const float*)d_in[23];
    const float* arel2 = (const float*)d_in[24];
    const float* mrel2 = (const float*)d_in[25];
    const float* prel2 = (const float*)d_in[26];
    const float* Wlin = (const float*)d_in[27]; const float* blin = (const float*)d_in[28];
    float* out = (float*)d_out;

    cudaFuncSetAttribute(gemm_bf, cudaFuncAttributeMaxDynamicSharedMemorySize, GSMEM_BYTES);

    bf16* BB = nullptr;
    float* FF = nullptr;
    cudaGetSymbolAddress((void**)&BB, g_bf);
    cudaGetSymbolAddress((void**)&FF, g_f32);

    bf16* XB = BB + OB_XB;
    bf16* WKQV1 = BB + OB_WKQV1; bf16* WA1B = BB + OB_WA1;
    bf16* AREL1B = BB + OB_AREL1; bf16* MREL1B = BB + OB_MREL1;
    bf16* WKQV2 = BB + OB_WKQV2; bf16* WA2B = BB + OB_WA2;
    bf16* AREL2B = BB + OB_AREL2; bf16* MREL2B = BB + OB_MREL2;
    bf16* KQV1 = BB + OB_KQV1; bf16* KR1 = BB + OB_KR1; bf16* VR1 = BB + OB_VR1;
    bf16* ACT1 = BB + OB_ACT1; bf16* H1 = BB + OB_H1;
    bf16* KQV2 = BB + OB_KQV2; bf16* KR2 = BB + OB_KR2; bf16* VR2 = BB + OB_VR2;
    bf16* ACT2 = BB + OB_ACT2; bf16* H2 = BB + OB_H2;

    float* OUT1 = FF + OF_OUT1; float* OUT2 = FF + OF_OUT2;
    float* ALPHA = FF + OF_ALPHA; float* SB = FF + OF_SB;
    float* BKQV1 = FF + OF_BKQV1; float* BKQV2 = FF + OF_BKQV2;

    const int st[4] = {0, 0, 1, 1};
    const int dt[4] = {0, 1, 0, 1};
    const int ewb = (EE * NH * 32 + 255) / 256;

    // ---- conversion / packing ----
    cvt_bf4<<<2048, 256>>>(x, XB, (size_t)TT * NN * F0 / 4);
    pack3w<<<2048, 256>>>(Wk1, Wq1, Wv1, WKQV1, F0, F1);
    pack3b<<<24, 256>>>(bk1, bq1, bv1, BKQV1, F1);
    cvt_bf4<<<512, 256>>>(Wa1, WA1B, (size_t)TT * F1 * F1 / 4);
    cvt_bf4<<<512, 256>>>(arel1, AREL1B, (size_t)4 * NH * D1 * D1 / 4);
    cvt_bf4<<<512, 256>>>(mrel1, MREL1B, (size_t)4 * NH * D1 * D1 / 4);
    pack3w<<<1024, 256>>>(Wk2, Wq2, Wv2, WKQV2, F1, F2);
    pack3b<<<12, 256>>>(bk2, bq2, bv2, BKQV2, F2);
    cvt_bf4<<<512, 256>>>(Wa2, WA2B, (size_t)TT * F2 * F2 / 4);
    cvt_bf4<<<128, 256>>>(arel2, AREL2B, (size_t)4 * NH * D2 * D2 / 4);
    cvt_bf4<<<128, 256>>>(mrel2, MREL2B, (size_t)4 * NH * D2 * D2 / 4);

    // ============ LAYER 1 ============
    // fused K|Q|V projection: [T,N,2048] @ [T,2048,3072] -> KQV1 [T,N,3072]
    gemm(XB, WKQV1, BKQV1, KQV1, NN, 3 * F1, F0, F0, 3 * F1, 3 * F1,
         (size_t)NN * F0, (size_t)F0 * 3 * F1, 3 * F1, (size_t)NN * 3 * F1, TT);

    // rel transforms, batched over heads (A z-stride = head offset)
    for (int e = 0; e < 4; e++) {
        const bf16* Kbase = KQV1 + (size_t)st[e] * NN * 3 * F1;          // K section
        const bf16* Vbase = Kbase + 2 * F1;                              // V section
        gemm(Kbase, AREL1B + (size_t)e * NH * D1 * D1, nullptr, KR1 + (size_t)e * NN * F1,
             NN, D1, D1, 3 * F1, D1, F1,
             (size_t)D1, (size_t)D1 * D1, 0, (size_t)D1, NH);
        gemm(Vbase, MREL1B + (size_t)e * NH * D1 * D1, nullptr, VR1 + (size_t)e * NN * F1,
             NN, D1, D1, 3 * F1, D1, F1,
             (size_t)D1, (size_t)D1 * D1, 0, (size_t)D1, NH);
    }

    fill_f<<<512, 256>>>(SB, 0.f, 4 * NN * NH);
    fill_f<<<2048, 256>>>(OUT1, 0.f, TT * NN * F1);
    {
        float scale = 1.f / sqrtf((float)D1);
        for (int e = 0; e < 4; e++)
            edge_logits<D1><<<ewb, 256>>>(KQV1 + (size_t)dt[e] * NN * 3 * F1 + F1, 3 * F1,
                KR1 + (size_t)e * NN * F1, F1, ei[e], ei[e] + EE, prel1 + e * NH,
                ALPHA + (size_t)e * EE * NH, SB + (size_t)e * NN * NH, scale);
        for (int e = 0; e < 4; e++)
            edge_aggregate<D1><<<ewb, 256>>>(VR1 + (size_t)e * NN * F1, F1,
                ei[e], ei[e] + EE, ALPHA + (size_t)e * EE * NH, SB + (size_t)e * NN * NH,
                OUT1 + (size_t)dt[e] * NN * F1, F1);
    }

    gelu_bf<<<2048, 256>>>(OUT1, ACT1, TT * NN * F1);
    gemm(ACT1, WA1B, ba1, H1, NN, F1, F1, F1, F1, F1,
         (size_t)NN * F1, (size_t)F1 * F1, F1, (size_t)NN * F1, TT);

    // ============ LAYER 2 ============
    gemm(H1, WKQV2, BKQV2, KQV2, NN, 3 * F2, F1, F1, 3 * F2, 3 * F2,
         (size_t)NN * F1, (size_t)F1 * 3 * F2, 3 * F2, (size_t)NN * 3 * F2, TT);

    for (int e = 0; e < 4; e++) {
        const bf16* Kbase = KQV2 + (size_t)st[e] * NN * 3 * F2;
        const bf16* Vbase = Kbase + 2 * F2;
        gemm(Kbase, AREL2B + (size_t)e * NH * D2 * D2, nullptr, KR2 + (size_t)e * NN * F2,
             NN, D2, D2, 3 * F2, D2, F2,
             (size_t)D2, (size_t)D2 * D2, 0, (size_t)D2, NH);
        gemm(Vbase, MREL2B + (size_t)e * NH * D2 * D2, nullptr, VR2 + (size_t)e * NN * F2,
             NN, D2, D2, 3 * F2, D2, F2,
             (size_t)D2, (size_t)D2 * D2, 0, (size_t)D2, NH);
    }

    fill_f<<<512, 256>>>(SB, 0.f, 4 * NN * NH);
    fill_f<<<2048, 256>>>(OUT2, 0.f, TT * NN * F2);
    {
        float scale = 1.f / sqrtf((float)D2);
        for (int e = 0; e < 4; e++)
            edge_logits<D2><<<ewb, 256>>>(KQV2 + (size_t)dt[e] * NN * 3 * F2 + F2, 3 * F2,
                KR2 + (size_t)e * NN * F2, F2, ei[e], ei[e] + EE, prel2 + e * NH,
                ALPHA + (size_t)e * EE * NH, SB + (size_t)e * NN * NH, scale);
        for (int e = 0; e < 4; e++)
            edge_aggregate<D2><<<ewb, 256>>>(VR2 + (size_t)e * NN * F2, F2,
                ei[e], ei[e] + EE, ALPHA + (size_t)e * EE * NH, SB + (size_t)e * NN * NH,
                OUT2 + (size_t)dt[e] * NN * F2, F2);
    }

    gelu_bf<<<2048, 256>>>(OUT2, ACT2, TT * NN * F2);
    gemm(ACT2, WA2B, ba2, H2, NN, F2, F2, F2, F2, F2,
         (size_t)NN * F2, (size_t)F2 * F2, F2, (size_t)NN * F2, TT);

    // ============ final ============
    final_kernel<<<(TT * NN * 32 + 255) / 256, 256>>>(H2, Wlin, blin, out);
}

// round 9
// speedup vs baseline: 7.6613x; 1.2528x over previous
#include <cuda_runtime.h>
#include <cuda_bf16.h>
#include <math.h>
#include <stdint.h>

// ---------------- problem constants ----------------
#define NN 10000
#define EE 60000
#define TT 2
#define NH 8
#define F0 2048
#define F1 1024
#define D1 128
#define F2 512
#define D2 64
#define OUTF 8

typedef __nv_bfloat16 bf16;
typedef __nv_bfloat162 bf162;

// ---------------- bf16 scratch offsets (elements) ----------------
#define OB_XB      ((size_t)0)                               // TT*NN*F0
#define OB_WKQV1   (OB_XB + (size_t)TT*NN*F0)                // TT*F0*3F1
#define OB_WA1     (OB_WKQV1 + (size_t)TT*F0*3*F1)
#define OB_AREL1   (OB_WA1 + (size_t)TT*F1*F1)
#define OB_MREL1   (OB_AREL1 + (size_t)4*NH*D1*D1)           // must follow AREL1
#define OB_WKQV2   (OB_MREL1 + (size_t)4*NH*D1*D1)
#define OB_WA2     (OB_WKQV2 + (size_t)TT*F1*3*F2)
#define OB_AREL2   (OB_WA2 + (size_t)TT*F2*F2)
#define OB_MREL2   (OB_AREL2 + (size_t)4*NH*D2*D2)           // must follow AREL2
#define OB_KQV1    (OB_MREL2 + (size_t)4*NH*D2*D2)           // TT*NN*3F1
#define OB_KR1     (OB_KQV1 + (size_t)TT*NN*3*F1)            // 4*NN*F1
#define OB_VR1     (OB_KR1 + (size_t)4*NN*F1)                // must follow KR1
#define OB_ACT1    (OB_VR1 + (size_t)4*NN*F1)                // TT*NN*F1
#define OB_H1      (OB_ACT1 + (size_t)TT*NN*F1)
#define OB_KQV2    (OB_H1 + (size_t)TT*NN*F1)                // TT*NN*3F2
#define OB_KR2     (OB_KQV2 + (size_t)TT*NN*3*F2)
#define OB_VR2     (OB_KR2 + (size_t)4*NN*F2)                // must follow KR2
#define OB_ACT2    (OB_VR2 + (size_t)4*NN*F2)
#define OB_H2      (OB_ACT2 + (size_t)TT*NN*F2)
#define OB_TOTAL   (OB_H2 + (size_t)TT*NN*F2)

__device__ bf16 g_bf[OB_TOTAL];

// ---------------- fp32 scratch ----------------
#define OF_OUTE   ((size_t)0)                                // 4*NN*F1 (layer1; reused for layer2)
#define OF_SB     (OF_OUTE + (size_t)4*NN*F1)                // 4*NN*NH
#define OF_BKQV1  (OF_SB + (size_t)4*NN*NH)                  // TT*3F1
#define OF_BKQV2  (OF_BKQV1 + (size_t)TT*3*F1)               // TT*3F2
#define OF_TOTAL  (OF_BKQV2 + (size_t)TT*3*F2)

__device__ float g_f32[OF_TOTAL];

// ---------------- asm helpers ----------------
__device__ __forceinline__ uint32_t smem_u32(const void* p) {
    return (uint32_t)__cvta_generic_to_shared(p);
}
__device__ __forceinline__ void cp16(uint32_t dst, const void* src, int sz) {
    asm volatile("cp.async.cg.shared.global [%0], [%1], 16, %2;" :: "r"(dst), "l"(src), "r"(sz));
}
__device__ __forceinline__ void cp_commit() { asm volatile("cp.async.commit_group;"); }
template<int N> __device__ __forceinline__ void cp_wait() {
    asm volatile("cp.async.wait_group %0;" :: "n"(N));
}
__device__ __forceinline__ void ldsm4(uint32_t& r0, uint32_t& r1, uint32_t& r2, uint32_t& r3, uint32_t a) {
    asm volatile("ldmatrix.sync.aligned.m8n8.x4.shared.b16 {%0,%1,%2,%3}, [%4];"
                 : "=r"(r0), "=r"(r1), "=r"(r2), "=r"(r3) : "r"(a));
}
__device__ __forceinline__ void ldsm4t(uint32_t& r0, uint32_t& r1, uint32_t& r2, uint32_t& r3, uint32_t a) {
    asm volatile("ldmatrix.sync.aligned.m8n8.x4.trans.shared.b16 {%0,%1,%2,%3}, [%4];"
                 : "=r"(r0), "=r"(r1), "=r"(r2), "=r"(r3) : "r"(a));
}
__device__ __forceinline__ void mma_bf16(float* c, const uint32_t* a, const uint32_t* b) {
    asm volatile("mma.sync.aligned.m16n8k16.row.col.f32.bf16.bf16.f32 "
                 "{%0,%1,%2,%3}, {%4,%5,%6,%7}, {%8,%9}, {%0,%1,%2,%3};"
                 : "+f"(c[0]), "+f"(c[1]), "+f"(c[2]), "+f"(c[3])
                 : "r"(a[0]), "r"(a[1]), "r"(a[2]), "r"(a[3]), "r"(b[0]), "r"(b[1]));
}

// ---------------- conversion / pack kernels ----------------
__global__ void cvt_bf4(const float* __restrict__ in, bf16* __restrict__ out, size_t n4) {
    size_t stride = (size_t)gridDim.x * blockDim.x;
    for (size_t i = (size_t)blockIdx.x * blockDim.x + threadIdx.x; i < n4; i += stride) {
        float4 v = ((const float4*)in)[i];
        bf162 a, b;
        a.x = __float2bfloat16(v.x); a.y = __float2bfloat16(v.y);
        b.x = __float2bfloat16(v.z); b.y = __float2bfloat16(v.w);
        ((bf162*)out)[i * 2] = a;
        ((bf162*)out)[i * 2 + 1] = b;
    }
}

// pack 3 weight matrices [T,Kd,Fo] along N -> out [T,Kd,3*Fo] bf16
__global__ void pack3w(const float* __restrict__ Wk, const float* __restrict__ Wq,
                       const float* __restrict__ Wv, bf16* __restrict__ out, int Kd, int Fo) {
    size_t total4 = (size_t)TT * Kd * 3 * Fo / 4;
    size_t stride = (size_t)gridDim.x * blockDim.x;
    for (size_t i = (size_t)blockIdx.x * blockDim.x + threadIdx.x; i < total4; i += stride) {
        size_t idx = i * 4;
        int j = (int)(idx % (size_t)(3 * Fo));
        size_t tk = idx / (size_t)(3 * Fo);
        int m = j / Fo, c = j % Fo;
        const float* W = (m == 0) ? Wk : ((m == 1) ? Wq : Wv);
        float4 v = *(const float4*)(W + tk * Fo + c);
        bf162 a, b;
        a.x = __float2bfloat16(v.x); a.y = __float2bfloat16(v.y);
        b.x = __float2bfloat16(v.z); b.y = __float2bfloat16(v.w);
        bf162* o = (bf162*)(out + idx);
        o[0] = a; o[1] = b;
    }
}

__global__ void pack3b(const float* __restrict__ bk, const float* __restrict__ bq,
                       const float* __restrict__ bv, float* __restrict__ out, int Fo) {
    int total = TT * 3 * Fo;
    for (int i = blockIdx.x * blockDim.x + threadIdx.x; i < total; i += gridDim.x * blockDim.x) {
        int j = i % (3 * Fo), t = i / (3 * Fo);
        int m = j / Fo, c = j % Fo;
        const float* b = (m == 0) ? bk : ((m == 1) ? bq : bv);
        out[i] = b[t * Fo + c];
    }
}

__global__ void fill_f(float* p, float v, int n) {
    int i = blockIdx.x * blockDim.x + threadIdx.x;
    int stride = gridDim.x * blockDim.x;
    for (; i < n; i += stride) p[i] = v;
}

// ---------------- bf16 tensor-core GEMM, 4-stage cp.async + ldmatrix ----------------
// C[z](bf16) = A[z](bf16)[M,lda] @ B[z](bf16)[K,ldb] + bias[z](fp32)
// Two-level batch strides: X += (z&7)*sX + (z>>3)*sX2.
// Tile 128x128x32; 8 warps: 2(M) x 4(N); warp tile 64x32.
#define GSTAGES 4
#define GSMEM_BYTES (GSTAGES * (128 * 40 + 32 * 136) * 2)

__global__ __launch_bounds__(256, 2)
void gemm_bf(const bf16* __restrict__ A, const bf16* __restrict__ B,
             const float* __restrict__ bias, bf16* __restrict__ C,
             int M, int Nn, int K, int lda, int ldb, int ldc,
             size_t sA, size_t sA2, size_t sB, size_t sB2,
             size_t sBias, size_t sC, size_t sC2)
{
    extern __shared__ char dynsmem[];
    bf16 (*As)[128][40] = (bf16(*)[128][40])dynsmem;
    bf16 (*Bs)[32][136] = (bf16(*)[32][136])(dynsmem + GSTAGES * 128 * 40 * 2);

    int z = blockIdx.z;
    int zl = z & 7, zh = z >> 3;
    A += (size_t)zl * sA + (size_t)zh * sA2;
    B += (size_t)zl * sB + (size_t)zh * sB2;
    C += (size_t)zl * sC + (size_t)zh * sC2;
    if (bias) bias += (size_t)zl * sBias;

    int bm = blockIdx.y * 128, bn = blockIdx.x * 128;
    int tid = threadIdx.x;
    int lane = tid & 31;
    int w = tid >> 5;
    int wm = (w & 1) * 64;
    int wn = (w >> 1) * 32;
    int tg = lane & 3;
    int rowg = lane >> 2;

    float acc[4][4][4];
#pragma unroll
    for (int i = 0; i < 4; i++)
#pragma unroll
        for (int j = 0; j < 4; j++)
#pragma unroll
            for (int r = 0; r < 4; r++) acc[i][j][r] = 0.f;

    const int nk = K / 32;

#define GLOAD(kt, s)                                                                   \
    do {                                                                               \
        _Pragma("unroll")                                                              \
        for (int p = 0; p < 2; p++) {                                                  \
            int idx = tid + p * 256;                                                   \
            int m = idx >> 2, c = (idx & 3) * 8;                                       \
            int gm = bm + m;                                                           \
            const bf16* sp = A + (size_t)(gm < M ? gm : 0) * lda + (kt) + c;           \
            cp16(smem_u32(&As[s][m][c]), sp, gm < M ? 16 : 0);                         \
        }                                                                              \
        _Pragma("unroll")                                                              \
        for (int p = 0; p < 2; p++) {                                                  \
            int idx = tid + p * 256;                                                   \
            int kr = idx >> 4, c = (idx & 15) * 8;                                     \
            int gn = bn + c;                                                           \
            const bf16* sp = B + (size_t)((kt) + kr) * ldb + (gn < Nn ? gn : 0);       \
            cp16(smem_u32(&Bs[s][kr][c]), sp, gn < Nn ? 16 : 0);                       \
        }                                                                              \
    } while (0)

#pragma unroll
    for (int s = 0; s < GSTAGES - 1; s++) {
        if (s < nk) GLOAD(s * 32, s);
        cp_commit();
    }

    for (int it = 0; it < nk; it++) {
        cp_wait<GSTAGES - 2>();
        __syncthreads();
        int nxt = it + GSTAGES - 1;
        int slot = nxt % GSTAGES;
        if (nxt < nk) GLOAD(nxt * 32, slot);
        cp_commit();

        int cur = it % GSTAGES;
#pragma unroll
        for (int ks = 0; ks < 2; ks++) {
            int k0 = ks * 16;
            uint32_t af[4][4], bfr[4][2];
#pragma unroll
            for (int mt = 0; mt < 4; mt++) {
                int row = wm + mt * 16 + (lane & 15);
                int coff = k0 + ((lane >> 4) << 3);
                ldsm4(af[mt][0], af[mt][1], af[mt][2], af[mt][3],
                      smem_u32(&As[cur][row][coff]));
            }
#pragma unroll
            for (int ntp = 0; ntp < 2; ntp++) {
                int row = k0 + (lane & 7) + ((lane >> 3) & 1) * 8;
                int col = wn + ntp * 16 + ((lane >> 4) << 3);
                uint32_t r0, r1, r2, r3;
                ldsm4t(r0, r1, r2, r3, smem_u32(&Bs[cur][row][col]));
                bfr[ntp * 2][0] = r0; bfr[ntp * 2][1] = r1;
                bfr[ntp * 2 + 1][0] = r2; bfr[ntp * 2 + 1][1] = r3;
            }
#pragma unroll
            for (int mt = 0; mt < 4; mt++)
#pragma unroll
                for (int nt = 0; nt < 4; nt++)
                    mma_bf16(acc[mt][nt], af[mt], bfr[nt]);
        }
    }
#undef GLOAD

    // epilogue: +bias, convert to bf16
#pragma unroll
    for (int mt = 0; mt < 4; mt++) {
#pragma unroll
        for (int nt = 0; nt < 4; nt++) {
            int gm0 = bm + wm + mt * 16 + rowg;
            int gn0 = bn + wn + nt * 8 + tg * 2;
            if (gn0 >= Nn) continue;
            float b0 = 0.f, b1 = 0.f;
            if (bias) { b0 = bias[gn0]; b1 = bias[gn0 + 1]; }
            if (gm0 < M) {
                bf162 v;
                v.x = __float2bfloat16(acc[mt][nt][0] + b0);
                v.y = __float2bfloat16(acc[mt][nt][1] + b1);
                *(bf162*)(C + (size_t)gm0 * ldc + gn0) = v;
            }
            if (gm0 + 8 < M) {
                bf162 v;
                v.x = __float2bfloat16(acc[mt][nt][2] + b0);
                v.y = __float2bfloat16(acc[mt][nt][3] + b1);
                *(bf162*)(C + (size_t)(gm0 + 8) * ldc + gn0) = v;
            }
        }
    }
}

// ---------------- fused edge kernel ----------------
// warp per (edge, head): logit = q.k; ex = exp(logit*p*scale);
// sum atomics + unnormalized ex*v scatter in one pass.
template<int D>
__global__ void edge_fused(const bf16* __restrict__ q, int ldq,
                           const bf16* __restrict__ kr,
                           const bf16* __restrict__ vr, int ldf,
                           const int* __restrict__ src, const int* __restrict__ dst,
                           const float* __restrict__ prel_row,
                           float* __restrict__ sbuf, float* __restrict__ oute,
                           float scale)
{
    int warp = (blockIdx.x * blockDim.x + threadIdx.x) >> 5;
    int lane = threadIdx.x & 31;
    if (warp >= EE * NH) return;
    int ed = warp / NH, h = warp % NH;
    int sN = src[ed], dN = dst[ed];
    const bf162* qp = (const bf162*)(q + (size_t)dN * ldq + h * D);
    const bf162* kp = (const bf162*)(kr + (size_t)sN * ldf + h * D);
    const bf162* vp = (const bf162*)(vr + (size_t)sN * ldf + h * D);

    float acc;
    float4 vv;
    if (D == 128) {
        bf162 q0 = qp[lane * 2], q1 = qp[lane * 2 + 1];
        bf162 k0 = kp[lane * 2], k1 = kp[lane * 2 + 1];
        bf162 v0 = vp[lane * 2], v1 = vp[lane * 2 + 1];
        float2 a0 = __bfloat1622float2(q0), a1 = __bfloat1622float2(q1);
        float2 b0 = __bfloat1622float2(k0), b1 = __bfloat1622float2(k1);
        float2 c0 = __bfloat1622float2(v0), c1 = __bfloat1622float2(v1);
        acc = a0.x * b0.x + a0.y * b0.y + a1.x * b1.x + a1.y * b1.y;
        vv = make_float4(c0.x, c0.y, c1.x, c1.y);
    } else {
        bf162 q0 = qp[lane], k0 = kp[lane], v0 = vp[lane];
        float2 a = __bfloat1622float2(q0);
        float2 b = __bfloat1622float2(k0);
        float2 c = __bfloat1622float2(v0);
        acc = a.x * b.x + a.y * b.y;
        vv = make_float4(c.x, c.y, 0.f, 0.f);
    }
#pragma unroll
    for (int o = 16; o; o >>= 1) acc += __shfl_xor_sync(0xFFFFFFFFu, acc, o);
    float ex = expf(acc * prel_row[h] * scale);
    if (lane == 0) atomicAdd(&sbuf[(size_t)dN * NH + h], ex);
    float* op = oute + (size_t)dN * ldf + h * D;
    if (D == 128) {
        atomicAdd((float4*)(op + lane * 4),
                  make_float4(vv.x * ex, vv.y * ex, vv.z * ex, vv.w * ex));
    } else {
        atomicAdd((float2*)(op + lane * 2), make_float2(vv.x * ex, vv.y * ex));
    }
}

// ---------------- combine two edge-type buffers: normalize + gelu -> bf16 ----------------
template<int D>
__global__ void combine_gelu(const float* __restrict__ in0, const float* __restrict__ in1,
                             const float* __restrict__ s0, const float* __restrict__ s1,
                             bf16* __restrict__ out, int total, int F)
{
    int i4 = blockIdx.x * blockDim.x + threadIdx.x;
    int stride = gridDim.x * blockDim.x;
    int n4 = total / 4;
    for (; i4 < n4; i4 += stride) {
        int i = i4 * 4;
        int node = i / F;
        int h = (i % F) / D;
        float inv0 = 1.f / (s0[node * NH + h] + 1e-16f);
        float inv1 = 1.f / (s1[node * NH + h] + 1e-16f);
        float4 a = ((const float4*)in0)[i4];
        float4 b = ((const float4*)in1)[i4];
        float x0 = a.x * inv0 + b.x * inv1;
        float x1 = a.y * inv0 + b.y * inv1;
        float x2 = a.z * inv0 + b.z * inv1;
        float x3 = a.w * inv0 + b.w * inv1;
        bf162 r0, r1;
        r0.x = __float2bfloat16(0.5f * x0 * (1.0f + erff(x0 * 0.70710678f)));
        r0.y = __float2bfloat16(0.5f * x1 * (1.0f + erff(x1 * 0.70710678f)));
        r1.x = __float2bfloat16(0.5f * x2 * (1.0f + erff(x2 * 0.70710678f)));
        r1.y = __float2bfloat16(0.5f * x3 * (1.0f + erff(x3 * 0.70710678f)));
        ((bf162*)(out + i))[0] = r0;
        ((bf162*)(out + i))[1] = r1;
    }
}

// ---------------- final linear + row softmax (bf16 h2) ----------------
__global__ void final_kernel(const bf16* __restrict__ h2, const float* __restrict__ W,
                             const float* __restrict__ b, float* __restrict__ out)
{
    int warp = (blockIdx.x * blockDim.x + threadIdx.x) >> 5;
    int lane = threadIdx.x & 31;
    if (warp >= TT * NN) return;
    const bf16* hp = h2 + (size_t)warp * F2;
    float acc[OUTF];
#pragma unroll
    for (int o = 0; o < OUTF; o++) acc[o] = 0.f;
    for (int f = lane; f < F2; f += 32) {
        float xv = __bfloat162float(hp[f]);
        const float* wp = W + (size_t)f * OUTF;
#pragma unroll
        for (int o = 0; o < OUTF; o++) acc[o] = fmaf(xv, wp[o], acc[o]);
    }
#pragma unroll
    for (int o = 0; o < OUTF; o++) {
#pragma unroll
        for (int off = 16; off; off >>= 1) acc[o] += __shfl_down_sync(0xFFFFFFFFu, acc[o], off);
    }
    if (lane == 0) {
        float l[OUTF];
        float m = -1e30f;
#pragma unroll
        for (int o = 0; o < OUTF; o++) { l[o] = acc[o] + b[o]; m = fmaxf(m, l[o]); }
        float s = 0.f;
#pragma unroll
        for (int o = 0; o < OUTF; o++) { l[o] = expf(l[o] - m); s += l[o]; }
        float inv = 1.f / s;
        float* op = out + (size_t)warp * OUTF;
#pragma unroll
        for (int o = 0; o < OUTF; o++) op[o] = l[o] * inv;
    }
}

// ---------------- host launch helpers ----------------
static void gemm(const bf16* A, const bf16* B, const float* bias, bf16* C,
                 int M, int N, int K, int lda, int ldb, int ldc,
                 size_t sA, size_t sB, size_t sBias, size_t sC, int batch)
{
    dim3 grid((N + 127) / 128, (M + 127) / 128, batch);
    gemm_bf<<<grid, 256, GSMEM_BYTES>>>(A, B, bias, C, M, N, K, lda, ldb, ldc,
                                        sA, 0, sB, 0, sBias, sC, 0);
}

// fused K-rel + V-rel: batch 16 (z = mat*8 + h), two-level strides
static void gemm_rel(const bf16* A, const bf16* B, bf16* C,
                     int D, int F3, int F,
                     size_t sA2, size_t sB2, size_t sC2)
{
    dim3 grid(1, (NN + 127) / 128, 16);
    gemm_bf<<<grid, 256, GSMEM_BYTES>>>(A, B, nullptr, C, NN, D, D, F3, D, F,
                                        (size_t)D, sA2, (size_t)D * D, sB2,
                                        0, (size_t)D, sC2);
}

extern "C" void kernel_launch(void* const* d_in, const int* in_sizes, int n_in,
                              void* d_out, int out_size)
{
    (void)in_sizes; (void)n_in; (void)out_size;
    const float* x     = (const float*)d_in[0];
    const int* ei[4]   = {(const int*)d_in[1], (const int*)d_in[2],
                          (const int*)d_in[3], (const int*)d_in[4]};
    const float* Wk1 = (const float*)d_in[5];  const float* bk1 = (const float*)d_in[6];
    const float* Wq1 = (const float*)d_in[7];  const float* bq1 = (const float*)d_in[8];
    const float* Wv1 = (const float*)d_in[9];  const float* bv1 = (const float*)d_in[10];
    const float* Wa1 = (const float*)d_in[11]; const float* ba1 = (const float*)d_in[12];
    const float* arel1 = (const float*)d_in[13];
    const float* mrel1 = (const float*)d_in[14];
    const float* prel1 = (const float*)d_in[15];
    const float* Wk2 = (const float*)d_in[16]; const float* bk2 = (const float*)d_in[17];
    const float* Wq2 = (const float*)d_in[18]; const float* bq2 = (const float*)d_in[19];
    const float* Wv2 = (const float*)d_in[20]; const float* bv2 = (const float*)d_in[21];
    const float* Wa2 = (const float*)d_in[22]; const float* ba2 = (const float*)d_in[23];
    const float* arel2 = (const float*)d_in[24];
    const float* mrel2 = (const float*)d_in[25];
    const float* prel2 = (const float*)d_in[26];
    const float* Wlin = (const float*)d_in[27]; const float* blin = (const float*)d_in[28];
    float* out = (float*)d_out;

    cudaFuncSetAttribute(gemm_bf, cudaFuncAttributeMaxDynamicSharedMemorySize, GSMEM_BYTES);

    bf16* BB = nullptr;
    float* FF = nullptr;
    cudaGetSymbolAddress((void**)&BB, g_bf);
    cudaGetSymbolAddress((void**)&FF, g_f32);

    bf16* XB = BB + OB_XB;
    bf16* WKQV1 = BB + OB_WKQV1; bf16* WA1B = BB + OB_WA1;
    bf16* AREL1B = BB + OB_AREL1; bf16* MREL1B = BB + OB_MREL1;
    bf16* WKQV2 = BB + OB_WKQV2; bf16* WA2B = BB + OB_WA2;
    bf16* AREL2B = BB + OB_AREL2; bf16* MREL2B = BB + OB_MREL2;
    bf16* KQV1 = BB + OB_KQV1; bf16* KR1 = BB + OB_KR1; bf16* VR1 = BB + OB_VR1;
    bf16* ACT1 = BB + OB_ACT1; bf16* H1 = BB + OB_H1;
    bf16* KQV2 = BB + OB_KQV2; bf16* KR2 = BB + OB_KR2; bf16* VR2 = BB + OB_VR2;
    bf16* ACT2 = BB + OB_ACT2; bf16* H2 = BB + OB_H2;

    float* OUTE = FF + OF_OUTE;          // 4 per-edge-type accumulators (fp32)
    float* SB = FF + OF_SB;
    float* BKQV1 = FF + OF_BKQV1; float* BKQV2 = FF + OF_BKQV2;

    const int st[4] = {0, 0, 1, 1};
    const int dt[4] = {0, 1, 0, 1};
    const int ewb = (EE * NH * 32 + 255) / 256;
    (void)mrel1; (void)mrel2;

    // ---- conversions (ordered so that launch #6 == KQV1 GEMM for ncu -s 5 -c 1) ----
    cvt_bf4<<<2048, 256>>>(x, XB, (size_t)TT * NN * F0 / 4);                    // 1
    pack3w<<<2048, 256>>>(Wk1, Wq1, Wv1, WKQV1, F0, F1);                        // 2
    pack3b<<<24, 256>>>(bk1, bq1, bv1, BKQV1, F1);                              // 3
    cvt_bf4<<<512, 256>>>(arel1, AREL1B, (size_t)4 * NH * D1 * D1 / 4);         // 4
    cvt_bf4<<<512, 256>>>(mrel1, MREL1B, (size_t)4 * NH * D1 * D1 / 4);         // 5

    // ============ LAYER 1 ============
    // fused K|Q|V projection: [T,N,2048] @ [T,2048,3072] -> KQV1 [T,N,3072]    // 6 (profiled)
    gemm(XB, WKQV1, BKQV1, KQV1, NN, 3 * F1, F0, F0, 3 * F1, 3 * F1,
         (size_t)NN * F0, (size_t)F0 * 3 * F1, 3 * F1, (size_t)NN * 3 * F1, TT);

    // remaining conversions
    cvt_bf4<<<512, 256>>>(Wa1, WA1B, (size_t)TT * F1 * F1 / 4);
    pack3w<<<1024, 256>>>(Wk2, Wq2, Wv2, WKQV2, F1, F2);
    pack3b<<<12, 256>>>(bk2, bq2, bv2, BKQV2, F2);
    cvt_bf4<<<512, 256>>>(Wa2, WA2B, (size_t)TT * F2 * F2 / 4);
    cvt_bf4<<<128, 256>>>(arel2, AREL2B, (size_t)4 * NH * D2 * D2 / 4);
    cvt_bf4<<<128, 256>>>(mrel2, MREL2B, (size_t)4 * NH * D2 * D2 / 4);

    // rel transforms: one batch-16 launch per edge type (K batches z<8, V batches z>=8)
    for (int e = 0; e < 4; e++) {
        gemm_rel(KQV1 + (size_t)st[e] * NN * 3 * F1,
                 AREL1B + (size_t)e * NH * D1 * D1,
                 KR1 + (size_t)e * NN * F1,
                 D1, 3 * F1, F1,
                 (size_t)2 * F1,                 // A: V section offset
                 (size_t)4 * NH * D1 * D1,       // B: MREL1 - AREL1
                 (size_t)4 * NN * F1);           // C: VR1 - KR1
    }

    fill_f<<<512, 256>>>(SB, 0.f, 4 * NN * NH);
    fill_f<<<4096, 256>>>(OUTE, 0.f, 4 * NN * F1);
    {
        float scale = 1.f / sqrtf((float)D1);
        for (int e = 0; e < 4; e++)
            edge_fused<D1><<<ewb, 256>>>(KQV1 + (size_t)dt[e] * NN * 3 * F1 + F1, 3 * F1,
                KR1 + (size_t)e * NN * F1, VR1 + (size_t)e * NN * F1, F1,
                ei[e], ei[e] + EE, prel1 + e * NH,
                SB + (size_t)e * NN * NH, OUTE + (size_t)e * NN * F1, scale);
    }
    // combine (t0 <- e0,e2 ; t1 <- e1,e3), normalize + gelu -> bf16
    combine_gelu<D1><<<2048, 256>>>(OUTE, OUTE + (size_t)2 * NN * F1,
                                    SB, SB + (size_t)2 * NN * NH,
                                    ACT1, NN * F1, F1);
    combine_gelu<D1><<<2048, 256>>>(OUTE + (size_t)1 * NN * F1, OUTE + (size_t)3 * NN * F1,
                                    SB + (size_t)1 * NN * NH, SB + (size_t)3 * NN * NH,
                                    ACT1 + (size_t)NN * F1, NN * F1, F1);

    gemm(ACT1, WA1B, ba1, H1, NN, F1, F1, F1, F1, F1,
         (size_t)NN * F1, (size_t)F1 * F1, F1, (size_t)NN * F1, TT);

    // ============ LAYER 2 ============
    gemm(H1, WKQV2, BKQV2, KQV2, NN, 3 * F2, F1, F1, 3 * F2, 3 * F2,
         (size_t)NN * F1, (size_t)F1 * 3 * F2, 3 * F2, (size_t)NN * 3 * F2, TT);

    for (int e = 0; e < 4; e++) {
        gemm_rel(KQV2 + (size_t)st[e] * NN * 3 * F2,
                 AREL2B + (size_t)e * NH * D2 * D2,
                 KR2 + (size_t)e * NN * F2,
                 D2, 3 * F2, F2,
                 (size_t)2 * F2,
                 (size_t)4 * NH * D2 * D2,
                 (size_t)4 * NN * F2);
    }

    fill_f<<<512, 256>>>(SB, 0.f, 4 * NN * NH);
    fill_f<<<2048, 256>>>(OUTE, 0.f, 4 * NN * F2);
    {
        float scale = 1.f / sqrtf((float)D2);
        for (int e = 0; e < 4; e++)
            edge_fused<D2><<<ewb, 256>>>(KQV2 + (size_t)dt[e] * NN * 3 * F2 + F2, 3 * F2,
                KR2 + (size_t)e * NN * F2, VR2 + (size_t)e * NN * F2, F2,
                ei[e], ei[e] + EE, prel2 + e * NH,
                SB + (size_t)e * NN * NH, OUTE + (size_t)e * NN * F2, scale);
    }
    combine_gelu<D2><<<1024, 256>>>(OUTE, OUTE + (size_t)2 * NN * F2,
                                    SB, SB + (size_t)2 * NN * NH,
                                    ACT2, NN * F2, F2);
    combine_gelu<D2><<<1024, 256>>>(OUTE + (size_t)1 * NN * F2, OUTE + (size_t)3 * NN * F2,
                                    SB + (size_t)1 * NN * NH, SB + (size_t)3 * NN * NH,
                                    ACT2 + (size_t)NN * F2, NN * F2, F2);

    gemm(ACT2, WA2B, ba2, H2, NN, F2, F2, F2, F2, F2,
         (size_t)NN * F2, (size_t)F2 * F2, F2, (size_t)NN * F2, TT);

    // ============ final ============
    final_kernel<<<(TT * NN * 32 + 255) / 256, 256>>>(H2, Wlin, blin, out);
}